// round 1
// baseline (speedup 1.0000x reference)
#include <cuda_runtime.h>
#include <stdint.h>
#include <math.h>

// Problem constants (fixed by the dataset): N=100000, H=64, E=1600000, P=3
#define NMAX 100000
#define HDIM 64
#define PNUM 3

// ---------------- scratch (no allocation allowed -> device globals) -------
__device__ __align__(16) float g_fts[NMAX * HDIM];            // 25.6 MB
__device__ __align__(16) float g_emb[PNUM][NMAX * HDIM];      // 76.8 MB (pre-activation: agg + bias)
__device__ float g_s[PNUM * HDIM];                            // attention column sums
__device__ float g_beta[PNUM];

__device__ __forceinline__ float prelu_f(float x, float s) { return x > 0.f ? x : s * x; }

// ===========================================================================
// GCN GEMM: g_fts[n][j] = sum_k Xm[n][k] * W[j][k]
//   Xm = X with rows zeroed where mask[n] != 0 (mask may be null).
// Tile: 128 rows x 64 cols, 256 threads, thread tile 4 rows x 8 cols.
// smem layouts chosen so every LDS.128 phase is broadcast or 128B-contiguous.
// ===========================================================================
__global__ __launch_bounds__(256) void gemm_gcn(
    const float* __restrict__ X, const int* __restrict__ mask,
    const float* __restrict__ W, int n)
{
    __shared__ float4 xs[128][16];   // [row][k4]
    __shared__ float4 wst[16][64];   // [k4][col]  (col-contiguous -> conflict-free)
    int t = threadIdx.x;
    int rowBase = blockIdx.x * 128;

    // Load W (64x64) transposed into wst
#pragma unroll
    for (int q = 0; q < 4; q++) {
        int idx = t + q * 256;
        int c = idx >> 4, k = idx & 15;
        wst[k][c] = __ldg(((const float4*)W) + c * 16 + k);
    }
    // Load X tile (masked, zero-padded)
#pragma unroll
    for (int q = 0; q < 8; q++) {
        int idx = t + q * 256;
        int r = idx >> 4, k = idx & 15;
        int gr = rowBase + r;
        float4 v = make_float4(0.f, 0.f, 0.f, 0.f);
        if (gr < n) {
            bool zero = (mask != nullptr) && (mask[gr] != 0);
            if (!zero) v = __ldg(((const float4*)X) + gr * 16 + k);
        }
        xs[r][k] = v;
    }
    __syncthreads();

    int rg = t >> 3;   // 0..31 -> rows rg*4 .. rg*4+3
    int cg = t & 7;    // cols cg + 8*j
    float acc[4][8];
#pragma unroll
    for (int i = 0; i < 4; i++)
#pragma unroll
        for (int j = 0; j < 8; j++) acc[i][j] = 0.f;

#pragma unroll
    for (int k = 0; k < 16; k++) {
        float4 xv[4], wv[8];
#pragma unroll
        for (int i = 0; i < 4; i++) xv[i] = xs[rg * 4 + i][k];
#pragma unroll
        for (int j = 0; j < 8; j++) wv[j] = wst[k][cg + 8 * j];
#pragma unroll
        for (int i = 0; i < 4; i++)
#pragma unroll
            for (int j = 0; j < 8; j++) {
                acc[i][j] += xv[i].x * wv[j].x;
                acc[i][j] += xv[i].y * wv[j].y;
                acc[i][j] += xv[i].z * wv[j].z;
                acc[i][j] += xv[i].w * wv[j].w;
            }
    }

#pragma unroll
    for (int i = 0; i < 4; i++) {
        int gr = rowBase + rg * 4 + i;
        if (gr < n) {
#pragma unroll
            for (int j = 0; j < 8; j++) g_fts[gr * 64 + cg + 8 * j] = acc[i][j];
        }
    }
}

// ===========================================================================
// init agg buffer with bias broadcast (replaces memset; bias added pre-SpMM)
// ===========================================================================
__global__ void init_bias(int p, const float* __restrict__ b, int n)
{
    int idx = blockIdx.x * blockDim.x + threadIdx.x;
    if (idx >= n * 16) return;
    int j = idx & 15;
    ((float4*)g_emb[p])[idx] = __ldg(((const float4*)b) + j);
}

// ===========================================================================
// SpMM: g_emb[p][row[e]] += g_fts[col[e]] * vals[e]   (vector f32x4 reductions)
// 16 threads per edge, each handles one float4 of the 64-wide row.
// ===========================================================================
__global__ __launch_bounds__(256) void spmm(
    int p, const int* __restrict__ row, const int* __restrict__ col,
    const float* __restrict__ vals, int e)
{
    int tid = blockIdx.x * blockDim.x + threadIdx.x;
    int eidx = tid >> 4;
    if (eidx >= e) return;
    int l = tid & 15;
    int c = __ldg(col + eidx);
    int r = __ldg(row + eidx);
    float v = __ldg(vals + eidx);
    float4 m = __ldg(((const float4*)g_fts) + c * 16 + l);
    float* dst = &g_emb[p][r * 64 + l * 4];
    asm volatile("red.global.add.v4.f32 [%0], {%1,%2,%3,%4};"
                 :: "l"(dst), "f"(m.x * v), "f"(m.y * v), "f"(m.z * v), "f"(m.w * v)
                 : "memory");
}

// ===========================================================================
// Attention GEMM: per metapath p,
//   t[n][j] = tanh( sum_k prelu(emb_p[n][k]) * fcw[j][k] + fcb[j] )
//   g_s[p][j] += sum_n t[n][j]      (column sums; mean taken in softmax)
// Same tiling as gemm_gcn; PReLU fused into the smem load.
// ===========================================================================
__global__ __launch_bounds__(256) void att_gemm(
    int p, const float* __restrict__ a,
    const float* __restrict__ fcw, const float* __restrict__ fcb, int n)
{
    __shared__ float4 xs[128][16];
    __shared__ float4 wst[16][64];
    int t = threadIdx.x;
    int rowBase = blockIdx.x * 128;
    float sa = __ldg(a + p);

#pragma unroll
    for (int q = 0; q < 4; q++) {
        int idx = t + q * 256;
        int c = idx >> 4, k = idx & 15;
        wst[k][c] = __ldg(((const float4*)fcw) + c * 16 + k);
    }
    const float* E = g_emb[p];
#pragma unroll
    for (int q = 0; q < 8; q++) {
        int idx = t + q * 256;
        int r = idx >> 4, k = idx & 15;
        int gr = rowBase + r;
        float4 v = make_float4(0.f, 0.f, 0.f, 0.f);
        if (gr < n) {
            v = __ldg(((const float4*)E) + gr * 16 + k);
            v.x = prelu_f(v.x, sa); v.y = prelu_f(v.y, sa);
            v.z = prelu_f(v.z, sa); v.w = prelu_f(v.w, sa);
        }
        xs[r][k] = v;
    }
    __syncthreads();

    int rg = t >> 3, cg = t & 7;
    float acc[4][8];
#pragma unroll
    for (int i = 0; i < 4; i++)
#pragma unroll
        for (int j = 0; j < 8; j++) acc[i][j] = 0.f;

#pragma unroll
    for (int k = 0; k < 16; k++) {
        float4 xv[4], wv[8];
#pragma unroll
        for (int i = 0; i < 4; i++) xv[i] = xs[rg * 4 + i][k];
#pragma unroll
        for (int j = 0; j < 8; j++) wv[j] = wst[k][cg + 8 * j];
#pragma unroll
        for (int i = 0; i < 4; i++)
#pragma unroll
            for (int j = 0; j < 8; j++) {
                acc[i][j] += xv[i].x * wv[j].x;
                acc[i][j] += xv[i].y * wv[j].y;
                acc[i][j] += xv[i].z * wv[j].z;
                acc[i][j] += xv[i].w * wv[j].w;
            }
    }

    // tanh + bias, then per-thread column partials (only valid rows contribute)
    float colsum[8];
#pragma unroll
    for (int j = 0; j < 8; j++) colsum[j] = 0.f;
#pragma unroll
    for (int i = 0; i < 4; i++) {
        int gr = rowBase + rg * 4 + i;
        if (gr < n) {
#pragma unroll
            for (int j = 0; j < 8; j++)
                colsum[j] += tanhf(acc[i][j] + __ldg(fcb + cg + 8 * j));
        }
    }
    // reduce over the 4 rg values within the warp (lanes l, l^8, l^16, l^24)
#pragma unroll
    for (int j = 0; j < 8; j++) {
        colsum[j] += __shfl_xor_sync(0xffffffffu, colsum[j], 8);
        colsum[j] += __shfl_xor_sync(0xffffffffu, colsum[j], 16);
    }
    __syncthreads();                      // done with xs -> reuse as ssum
    float* ssum = reinterpret_cast<float*>(xs);
    if (t < 64) ssum[t] = 0.f;
    __syncthreads();
    if ((t & 31) < 8) {                   // lanes 0..7 of each warp hold warp sums
#pragma unroll
        for (int j = 0; j < 8; j++) atomicAdd(&ssum[cg + 8 * j], colsum[j]);
    }
    __syncthreads();
    if (t < 64) atomicAdd(&g_s[p * 64 + t], ssum[t]);
}

// ===========================================================================
__global__ void zero_s_k()
{
    int t = threadIdx.x;
    if (t < PNUM * HDIM) g_s[t] = 0.f;
}

__global__ void softmax_k(const float* __restrict__ att, int n)
{
    __shared__ float lg[PNUM];
    int t = threadIdx.x;
    int w = t >> 5, l = t & 31;
    if (w < PNUM) {
        float v = g_s[w * 64 + l] * __ldg(att + l)
                + g_s[w * 64 + 32 + l] * __ldg(att + 32 + l);
#pragma unroll
        for (int o = 16; o; o >>= 1) v += __shfl_down_sync(0xffffffffu, v, o);
        if (l == 0) lg[w] = v / (float)n;
    }
    __syncthreads();
    if (t == 0) {
        float m = fmaxf(lg[0], fmaxf(lg[1], lg[2]));
        float e0 = expf(lg[0] - m), e1 = expf(lg[1] - m), e2 = expf(lg[2] - m);
        float inv = 1.f / (e0 + e1 + e2);
        g_beta[0] = e0 * inv; g_beta[1] = e1 * inv; g_beta[2] = e2 * inv;
    }
}

// z[n][h] = sum_p beta_p * prelu(emb_p[n][h], a_p)
__global__ void combine_k(const float* __restrict__ a, float* __restrict__ out, int n)
{
    int idx = blockIdx.x * blockDim.x + threadIdx.x;
    if (idx >= n * 16) return;
    float b0 = g_beta[0], b1 = g_beta[1], b2 = g_beta[2];
    float s0 = __ldg(a), s1 = __ldg(a + 1), s2 = __ldg(a + 2);
    float4 e0 = ((const float4*)g_emb[0])[idx];
    float4 e1 = ((const float4*)g_emb[1])[idx];
    float4 e2 = ((const float4*)g_emb[2])[idx];
    float4 o;
    o.x = b0 * prelu_f(e0.x, s0) + b1 * prelu_f(e1.x, s1) + b2 * prelu_f(e2.x, s2);
    o.y = b0 * prelu_f(e0.y, s0) + b1 * prelu_f(e1.y, s1) + b2 * prelu_f(e2.y, s2);
    o.z = b0 * prelu_f(e0.z, s0) + b1 * prelu_f(e1.z, s1) + b2 * prelu_f(e2.z, s2);
    o.w = b0 * prelu_f(e0.w, s0) + b1 * prelu_f(e1.w, s1) + b2 * prelu_f(e2.w, s2);
    ((float4*)out)[idx] = o;
}

// ===========================================================================
extern "C" void kernel_launch(void* const* d_in, const int* in_sizes, int n_in,
                              void* d_out, int out_size)
{
    const float* h    = (const float*)d_in[0];
    const float* W    = (const float*)d_in[1];
    const float* b    = (const float*)d_in[2];
    const float* a    = (const float*)d_in[3];
    const float* fcw  = (const float*)d_in[4];
    const float* fcb  = (const float*)d_in[5];
    const float* att  = (const float*)d_in[6];
    const float* adj  = (const float*)d_in[7];
    const int*   row  = (const int*)d_in[8];
    const int*   col  = (const int*)d_in[9];
    const int*   mask1 = (const int*)d_in[10];
    const int*   mask2 = (const int*)d_in[11];

    int n = in_sizes[0] / HDIM;
    int e = in_sizes[7];

    float* out    = (float*)d_out;
    float* z_mp   = out;
    float* z_mp2  = out + (size_t)n * HDIM;
    float* x_rec  = out + (size_t)2 * n * HDIM;

    int gGemm = (n + 127) / 128;
    int gEW   = (n * 16 + 255) / 256;
    int gSp   = (int)(((long long)e * 16 + 255) / 256);

    auto run_pass = [&](const float* x, const int* mask, float* zout) {
        zero_s_k<<<1, 256>>>();
        for (int p = 0; p < PNUM; p++) {
            gemm_gcn<<<gGemm, 256>>>(x, mask, W + p * HDIM * HDIM, n);
            init_bias<<<gEW, 256>>>(p, b + p * HDIM, n);
            spmm<<<gSp, 256>>>(p, row, col, adj, e);
            att_gemm<<<gGemm, 256>>>(p, a, fcw, fcb, n);
        }
        softmax_k<<<1, 96>>>(att, n);
        combine_k<<<gEW, 256>>>(a, zout, n);
    };

    run_pass(h, mask1, z_mp);        // z_mp   (mask1 on input h)
    run_pass(h, nullptr, z_mp2);     // z_mp2  (no mask)
    run_pass(z_mp, mask2, x_rec);    // x_recon (mask2 on z_mp)
}

// round 2
// speedup vs baseline: 1.3776x; 1.3776x over previous
#include <cuda_runtime.h>
#include <stdint.h>
#include <math.h>

// Problem constants: N=100000, H=64, E=1600000, P=3
#define NMAX 100000
#define HDIM 64
#define PNUM 3

// ---------------- scratch (no allocation allowed -> device globals) -------
__device__ __align__(16) float g_fts[NMAX * HDIM];             // 25.6 MB
__device__ __align__(16) float g_embA[PNUM][NMAX * HDIM];      // pass1 / pass3 (pre-act: agg+bias)
__device__ __align__(16) float g_embB[PNUM][NMAX * HDIM];      // pass2
__device__ float g_s[2][PNUM * HDIM];                          // attention column sums (A,B)
__device__ float g_beta[2][PNUM];

__device__ __forceinline__ float prelu_f(float x, float s) { return x > 0.f ? x : s * x; }

// ===========================================================================
// GCN GEMM: g_fts[n][j] = sum_k X[n][k] * W[j][k]   (no masking here anymore;
// masking is applied at the SpMM gather side, which is exactly equivalent)
// ===========================================================================
__global__ __launch_bounds__(256) void gemm_gcn(
    const float* __restrict__ X, const float* __restrict__ W, int n)
{
    __shared__ float4 xs[128][16];   // [row][k4]
    __shared__ float4 wst[16][64];   // [k4][col]
    int t = threadIdx.x;
    int rowBase = blockIdx.x * 128;

#pragma unroll
    for (int q = 0; q < 4; q++) {
        int idx = t + q * 256;
        int c = idx >> 4, k = idx & 15;
        wst[k][c] = __ldg(((const float4*)W) + c * 16 + k);
    }
#pragma unroll
    for (int q = 0; q < 8; q++) {
        int idx = t + q * 256;
        int r = idx >> 4, k = idx & 15;
        int gr = rowBase + r;
        float4 v = make_float4(0.f, 0.f, 0.f, 0.f);
        if (gr < n) v = __ldg(((const float4*)X) + gr * 16 + k);
        xs[r][k] = v;
    }
    __syncthreads();

    int rg = t >> 3, cg = t & 7;
    float acc[4][8];
#pragma unroll
    for (int i = 0; i < 4; i++)
#pragma unroll
        for (int j = 0; j < 8; j++) acc[i][j] = 0.f;

#pragma unroll
    for (int k = 0; k < 16; k++) {
        float4 xv[4], wv[8];
#pragma unroll
        for (int i = 0; i < 4; i++) xv[i] = xs[rg * 4 + i][k];
#pragma unroll
        for (int j = 0; j < 8; j++) wv[j] = wst[k][cg + 8 * j];
#pragma unroll
        for (int i = 0; i < 4; i++)
#pragma unroll
            for (int j = 0; j < 8; j++) {
                acc[i][j] += xv[i].x * wv[j].x;
                acc[i][j] += xv[i].y * wv[j].y;
                acc[i][j] += xv[i].z * wv[j].z;
                acc[i][j] += xv[i].w * wv[j].w;
            }
    }

#pragma unroll
    for (int i = 0; i < 4; i++) {
        int gr = rowBase + rg * 4 + i;
        if (gr < n) {
#pragma unroll
            for (int j = 0; j < 8; j++) g_fts[gr * 64 + cg + 8 * j] = acc[i][j];
        }
    }
}

// ===========================================================================
// init agg buffers with bias broadcast. dual=1 -> init embA[p] AND embB[p].
// ===========================================================================
__global__ void init_bias(int p, int dual, const float* __restrict__ b, int n)
{
    int idx = blockIdx.x * blockDim.x + threadIdx.x;
    int tot = n * 16;
    if (idx >= tot * (dual ? 2 : 1)) return;
    int which = idx >= tot;
    int i = which ? idx - tot : idx;
    int j = i & 15;
    float4 v = __ldg(((const float4*)b) + j);
    if (which) ((float4*)g_embB[p])[i] = v;
    else       ((float4*)g_embA[p])[i] = v;
}

// ===========================================================================
// Fused SpMM for pass1+pass2 (shared fts = h@W^T):
//   embB[p][row[e]] += fts[col[e]]*val[e]                      (always)
//   embA[p][row[e]] += fts[col[e]]*val[e]   if !mask1[col[e]]  (masked input)
// 16 lanes per edge, 2 edges per thread (EPT=2) for MLP.
// ===========================================================================
__global__ __launch_bounds__(256) void spmm_dual(
    int p, const int* __restrict__ row, const int* __restrict__ col,
    const float* __restrict__ vals, const int* __restrict__ mask1, int e)
{
    int tid = blockIdx.x * blockDim.x + threadIdx.x;
    int l = tid & 15;
    int grp = tid >> 4;
    int e0 = grp * 2, e1 = e0 + 1;
    if (e0 >= e) return;
    bool has1 = (e1 < e);

    int c0 = __ldg(col + e0), r0 = __ldg(row + e0);
    float v0 = __ldg(vals + e0);
    int m0 = __ldg(mask1 + c0);
    int c1 = 0, r1 = 0, m1 = 1; float v1 = 0.f;
    if (has1) { c1 = __ldg(col + e1); r1 = __ldg(row + e1); v1 = __ldg(vals + e1); m1 = __ldg(mask1 + c1); }

    float4 f0 = __ldg(((const float4*)g_fts) + c0 * 16 + l);
    float4 f1 = has1 ? __ldg(((const float4*)g_fts) + c1 * 16 + l) : make_float4(0,0,0,0);
    f0.x *= v0; f0.y *= v0; f0.z *= v0; f0.w *= v0;
    f1.x *= v1; f1.y *= v1; f1.z *= v1; f1.w *= v1;

    float* dB0 = &g_embB[p][r0 * 64 + l * 4];
    asm volatile("red.global.add.v4.f32 [%0], {%1,%2,%3,%4};"
                 :: "l"(dB0), "f"(f0.x), "f"(f0.y), "f"(f0.z), "f"(f0.w) : "memory");
    if (has1) {
        float* dB1 = &g_embB[p][r1 * 64 + l * 4];
        asm volatile("red.global.add.v4.f32 [%0], {%1,%2,%3,%4};"
                     :: "l"(dB1), "f"(f1.x), "f"(f1.y), "f"(f1.z), "f"(f1.w) : "memory");
    }
    if (m0 == 0) {
        float* dA0 = &g_embA[p][r0 * 64 + l * 4];
        asm volatile("red.global.add.v4.f32 [%0], {%1,%2,%3,%4};"
                     :: "l"(dA0), "f"(f0.x), "f"(f0.y), "f"(f0.z), "f"(f0.w) : "memory");
    }
    if (has1 && m1 == 0) {
        float* dA1 = &g_embA[p][r1 * 64 + l * 4];
        asm volatile("red.global.add.v4.f32 [%0], {%1,%2,%3,%4};"
                     :: "l"(dA1), "f"(f1.x), "f"(f1.y), "f"(f1.z), "f"(f1.w) : "memory");
    }
}

// ===========================================================================
// Pass-3 SpMM: fts3[col]=0 whenever mask2[col] -> skip those edges entirely.
//   embA[p][row[e]] += fts[col[e]]*val[e]   if !mask2[col[e]]
// ===========================================================================
__global__ __launch_bounds__(256) void spmm_mask(
    int p, const int* __restrict__ row, const int* __restrict__ col,
    const float* __restrict__ vals, const int* __restrict__ mask2, int e)
{
    int tid = blockIdx.x * blockDim.x + threadIdx.x;
    int l = tid & 15;
    int grp = tid >> 4;
    int e0 = grp * 2, e1 = e0 + 1;
    if (e0 >= e) return;
    bool has1 = (e1 < e);

    int c0 = __ldg(col + e0);
    int m0 = __ldg(mask2 + c0);
    int c1 = 0, m1 = 1;
    if (has1) { c1 = __ldg(col + e1); m1 = __ldg(mask2 + c1); }

    if (m0 == 0) {
        int r0 = __ldg(row + e0); float v0 = __ldg(vals + e0);
        float4 f0 = __ldg(((const float4*)g_fts) + c0 * 16 + l);
        f0.x *= v0; f0.y *= v0; f0.z *= v0; f0.w *= v0;
        float* d0 = &g_embA[p][r0 * 64 + l * 4];
        asm volatile("red.global.add.v4.f32 [%0], {%1,%2,%3,%4};"
                     :: "l"(d0), "f"(f0.x), "f"(f0.y), "f"(f0.z), "f"(f0.w) : "memory");
    }
    if (has1 && m1 == 0) {
        int r1 = __ldg(row + e1); float v1 = __ldg(vals + e1);
        float4 f1 = __ldg(((const float4*)g_fts) + c1 * 16 + l);
        f1.x *= v1; f1.y *= v1; f1.z *= v1; f1.w *= v1;
        float* d1 = &g_embA[p][r1 * 64 + l * 4];
        asm volatile("red.global.add.v4.f32 [%0], {%1,%2,%3,%4};"
                     :: "l"(d1), "f"(f1.x), "f"(f1.y), "f"(f1.z), "f"(f1.w) : "memory");
    }
}

// ===========================================================================
// Attention GEMM: t[n][j] = tanh(sum_k prelu(emb[n][k]) * fcw[j][k] + fcb[j]),
// accumulate column sums into g_s[sel][p*64+j].
// ===========================================================================
__global__ __launch_bounds__(256) void att_gemm(
    int sel, int p, const float* __restrict__ a,
    const float* __restrict__ fcw, const float* __restrict__ fcb, int n)
{
    __shared__ float4 xs[128][16];
    __shared__ float4 wst[16][64];
    int t = threadIdx.x;
    int rowBase = blockIdx.x * 128;
    float sa = __ldg(a + p);
    const float* E = (sel == 0) ? g_embA[p] : g_embB[p];

#pragma unroll
    for (int q = 0; q < 4; q++) {
        int idx = t + q * 256;
        int c = idx >> 4, k = idx & 15;
        wst[k][c] = __ldg(((const float4*)fcw) + c * 16 + k);
    }
#pragma unroll
    for (int q = 0; q < 8; q++) {
        int idx = t + q * 256;
        int r = idx >> 4, k = idx & 15;
        int gr = rowBase + r;
        float4 v = make_float4(0.f, 0.f, 0.f, 0.f);
        if (gr < n) {
            v = __ldg(((const float4*)E) + gr * 16 + k);
            v.x = prelu_f(v.x, sa); v.y = prelu_f(v.y, sa);
            v.z = prelu_f(v.z, sa); v.w = prelu_f(v.w, sa);
        }
        xs[r][k] = v;
    }
    __syncthreads();

    int rg = t >> 3, cg = t & 7;
    float acc[4][8];
#pragma unroll
    for (int i = 0; i < 4; i++)
#pragma unroll
        for (int j = 0; j < 8; j++) acc[i][j] = 0.f;

#pragma unroll
    for (int k = 0; k < 16; k++) {
        float4 xv[4], wv[8];
#pragma unroll
        for (int i = 0; i < 4; i++) xv[i] = xs[rg * 4 + i][k];
#pragma unroll
        for (int j = 0; j < 8; j++) wv[j] = wst[k][cg + 8 * j];
#pragma unroll
        for (int i = 0; i < 4; i++)
#pragma unroll
            for (int j = 0; j < 8; j++) {
                acc[i][j] += xv[i].x * wv[j].x;
                acc[i][j] += xv[i].y * wv[j].y;
                acc[i][j] += xv[i].z * wv[j].z;
                acc[i][j] += xv[i].w * wv[j].w;
            }
    }

    float colsum[8];
#pragma unroll
    for (int j = 0; j < 8; j++) colsum[j] = 0.f;
#pragma unroll
    for (int i = 0; i < 4; i++) {
        int gr = rowBase + rg * 4 + i;
        if (gr < n) {
#pragma unroll
            for (int j = 0; j < 8; j++)
                colsum[j] += tanhf(acc[i][j] + __ldg(fcb + cg + 8 * j));
        }
    }
#pragma unroll
    for (int j = 0; j < 8; j++) {
        colsum[j] += __shfl_xor_sync(0xffffffffu, colsum[j], 8);
        colsum[j] += __shfl_xor_sync(0xffffffffu, colsum[j], 16);
    }
    __syncthreads();
    float* ssum = reinterpret_cast<float*>(xs);
    if (t < 64) ssum[t] = 0.f;
    __syncthreads();
    if ((t & 31) < 8) {
#pragma unroll
        for (int j = 0; j < 8; j++) atomicAdd(&ssum[cg + 8 * j], colsum[j]);
    }
    __syncthreads();
    if (t < 64) atomicAdd(&g_s[sel][p * 64 + t], ssum[t]);
}

// ===========================================================================
__global__ void zero_s_k(int both)
{
    int t = threadIdx.x;
    if (t < PNUM * HDIM) {
        g_s[0][t] = 0.f;
        if (both) g_s[1][t] = 0.f;
    }
}

__global__ void softmax_k(int both, const float* __restrict__ att, int n)
{
    // thread layout: warps 0..2 -> sel 0, warps 3..5 -> sel 1
    __shared__ float lg[2][PNUM];
    int t = threadIdx.x;
    int w = t >> 5, l = t & 31;
    int sel = w / PNUM, p = w % PNUM;
    if (w < PNUM * (both ? 2 : 1)) {
        float v = g_s[sel][p * 64 + l] * __ldg(att + l)
                + g_s[sel][p * 64 + 32 + l] * __ldg(att + 32 + l);
#pragma unroll
        for (int o = 16; o; o >>= 1) v += __shfl_down_sync(0xffffffffu, v, o);
        if (l == 0) lg[sel][p] = v / (float)n;
    }
    __syncthreads();
    if (t < (both ? 2 : 1) && (t == 0 || both)) {
        int s = t;
        float m = fmaxf(lg[s][0], fmaxf(lg[s][1], lg[s][2]));
        float e0 = expf(lg[s][0] - m), e1 = expf(lg[s][1] - m), e2 = expf(lg[s][2] - m);
        float inv = 1.f / (e0 + e1 + e2);
        g_beta[s][0] = e0 * inv; g_beta[s][1] = e1 * inv; g_beta[s][2] = e2 * inv;
    }
}

// z[n][h] = sum_p beta_p * prelu(emb_p[n][h], a_p)
__global__ void combine_k(int sel, const float* __restrict__ a, float* __restrict__ out, int n)
{
    int idx = blockIdx.x * blockDim.x + threadIdx.x;
    if (idx >= n * 16) return;
    float b0 = g_beta[sel][0], b1 = g_beta[sel][1], b2 = g_beta[sel][2];
    float s0 = __ldg(a), s1 = __ldg(a + 1), s2 = __ldg(a + 2);
    const float4* E0 = (const float4*)(sel == 0 ? g_embA[0] : g_embB[0]);
    const float4* E1 = (const float4*)(sel == 0 ? g_embA[1] : g_embB[1]);
    const float4* E2 = (const float4*)(sel == 0 ? g_embA[2] : g_embB[2]);
    float4 e0 = E0[idx], e1 = E1[idx], e2 = E2[idx];
    float4 o;
    o.x = b0 * prelu_f(e0.x, s0) + b1 * prelu_f(e1.x, s1) + b2 * prelu_f(e2.x, s2);
    o.y = b0 * prelu_f(e0.y, s0) + b1 * prelu_f(e1.y, s1) + b2 * prelu_f(e2.y, s2);
    o.z = b0 * prelu_f(e0.z, s0) + b1 * prelu_f(e1.z, s1) + b2 * prelu_f(e2.z, s2);
    o.w = b0 * prelu_f(e0.w, s0) + b1 * prelu_f(e1.w, s1) + b2 * prelu_f(e2.w, s2);
    ((float4*)out)[idx] = o;
}

// ===========================================================================
extern "C" void kernel_launch(void* const* d_in, const int* in_sizes, int n_in,
                              void* d_out, int out_size)
{
    const float* h     = (const float*)d_in[0];
    const float* W     = (const float*)d_in[1];
    const float* b     = (const float*)d_in[2];
    const float* a     = (const float*)d_in[3];
    const float* fcw   = (const float*)d_in[4];
    const float* fcb   = (const float*)d_in[5];
    const float* att   = (const float*)d_in[6];
    const float* adj   = (const float*)d_in[7];
    const int*   row   = (const int*)d_in[8];
    const int*   col   = (const int*)d_in[9];
    const int*   mask1 = (const int*)d_in[10];
    const int*   mask2 = (const int*)d_in[11];

    int n = in_sizes[0] / HDIM;
    int e = in_sizes[7];

    float* out   = (float*)d_out;
    float* z_mp  = out;
    float* z_mp2 = out + (size_t)n * HDIM;
    float* x_rec = out + (size_t)2 * n * HDIM;

    int gGemm = (n + 127) / 128;
    int gEW   = (n * 16 + 255) / 256;
    int gEW2  = (2 * n * 16 + 255) / 256;
    long long groups = ((long long)e + 1) / 2;
    int gSp   = (int)((groups * 16 + 255) / 256);

    // ------- pass 1 + pass 2 fused (shared fts = h @ W[p]^T) -------
    zero_s_k<<<1, 256>>>(1);
    for (int p = 0; p < PNUM; p++) {
        gemm_gcn<<<gGemm, 256>>>(h, W + p * HDIM * HDIM, n);
        init_bias<<<gEW2, 256>>>(p, 1, b + p * HDIM, n);
        spmm_dual<<<gSp, 256>>>(p, row, col, adj, mask1, e);
        att_gemm<<<gGemm, 256>>>(0, p, a, fcw, fcb, n);   // -> s[0] (z_mp)
        att_gemm<<<gGemm, 256>>>(1, p, a, fcw, fcb, n);   // -> s[1] (z_mp2)
    }
    softmax_k<<<1, 224>>>(1, att, n);
    combine_k<<<gEW, 256>>>(0, a, z_mp, n);
    combine_k<<<gEW, 256>>>(1, a, z_mp2, n);

    // ------- pass 3 (decode): input z_mp, mask2 applied at gather side -------
    zero_s_k<<<1, 256>>>(0);
    for (int p = 0; p < PNUM; p++) {
        gemm_gcn<<<gGemm, 256>>>(z_mp, W + p * HDIM * HDIM, n);
        init_bias<<<gEW, 256>>>(p, 0, b + p * HDIM, n);
        spmm_mask<<<gSp, 256>>>(p, row, col, adj, mask2, e);
        att_gemm<<<gGemm, 256>>>(0, p, a, fcw, fcb, n);
    }
    softmax_k<<<1, 224>>>(0, att, n);
    combine_k<<<gEW, 256>>>(0, a, x_rec, n);
}

// round 3
// speedup vs baseline: 1.7840x; 1.2950x over previous
#include <cuda_runtime.h>
#include <stdint.h>
#include <math.h>

// Problem constants: N=100000, H=64, E=1600000, P=3
#define NMAX 100000
#define EMAX 1600000
#define HDIM 64
#define PNUM 3

// ---------------- scratch (no allocation allowed -> device globals) -------
__device__ __align__(16) float g_fts[PNUM][NMAX * HDIM];   // 76.8 MB
__device__ __align__(16) float g_embA[PNUM][NMAX * HDIM];  // pass1 / pass3
__device__ __align__(16) float g_embB[PNUM][NMAX * HDIM];  // pass2
__device__ float g_s[2][PNUM * HDIM];
__device__ float g_beta[2][PNUM];

// CSR scratch (rebuilt every call; reused by all 9 SpMMs)
__device__ int   g_deg[NMAX];
__device__ int   g_off[NMAX + 1];
__device__ int   g_cur[NMAX];
__device__ int   g_cole[EMAX];
__device__ float g_vale[EMAX];
__device__ unsigned char g_mflags[EMAX];   // bit0 = mask1[col], bit1 = mask2[col]

__device__ __forceinline__ float prelu_f(float x, float s) { return x > 0.f ? x : s * x; }

// packed f32x2 FMA: d.lo += a.lo*b.lo ; d.hi += a.hi*b.hi
__device__ __forceinline__ void fma2(unsigned long long& d,
                                     unsigned long long a, unsigned long long b)
{
    asm("fma.rn.f32x2 %0, %1, %2, %3;" : "=l"(d) : "l"(a), "l"(b), "l"(d));
}
__device__ __forceinline__ float unpack_sum(unsigned long long v)
{
    float lo, hi;
    asm("mov.b64 {%0,%1}, %2;" : "=f"(lo), "=f"(hi) : "l"(v));
    return lo + hi;
}

// ===========================================================================
// CSR build
// ===========================================================================
__global__ void csr_zero(int n)
{
    int i = blockIdx.x * blockDim.x + threadIdx.x;
    if (i < n) g_deg[i] = 0;
}
__global__ void csr_hist(const int* __restrict__ row, int e)
{
    int i = blockIdx.x * blockDim.x + threadIdx.x;
    if (i < e) atomicAdd(&g_deg[row[i]], 1);
}
__global__ void csr_scan(int n)
{
    __shared__ int part[1024];
    int tid = threadIdx.x;
    int chunk = (n + 1023) >> 10;
    int beg = tid * chunk;
    int end = min(beg + chunk, n);
    int s = 0;
    for (int i = beg; i < end; i++) s += g_deg[i];
    part[tid] = s;
    __syncthreads();
    for (int o = 1; o < 1024; o <<= 1) {
        int t2 = (tid >= o) ? part[tid - o] : 0;
        __syncthreads();
        part[tid] += t2;
        __syncthreads();
    }
    int run = part[tid] - s;   // exclusive prefix
    for (int i = beg; i < end; i++) {
        g_off[i] = run; g_cur[i] = run;
        run += g_deg[i];
    }
    if (tid == 1023) g_off[n] = part[1023];
}
__global__ void csr_scatter(const int* __restrict__ row, const int* __restrict__ col,
                            const float* __restrict__ vals,
                            const int* __restrict__ mask1, const int* __restrict__ mask2,
                            int e)
{
    int i = blockIdx.x * blockDim.x + threadIdx.x;
    if (i >= e) return;
    int r = row[i], c = col[i];
    int pos = atomicAdd(&g_cur[r], 1);
    g_cole[pos] = c;
    g_vale[pos] = vals[i];
    g_mflags[pos] = (unsigned char)((mask1[c] ? 1 : 0) | (mask2[c] ? 2 : 0));
}

// ===========================================================================
// GCN GEMM (all p in one launch): g_fts[p][n][j] = sum_k X[n][k] * W[p][j][k]
// 128x64 tile, 256 thr, 4x8 thread tile, packed f32x2 FMA (pairs across k).
// ===========================================================================
__global__ __launch_bounds__(256) void gemm_gcn_all(
    const float* __restrict__ X, const float* __restrict__ Wall, int n)
{
    __shared__ ulonglong2 xs[128][16];   // [row][k4]  (k-quads natural pairs)
    __shared__ ulonglong2 wst[64][17];   // [col][k4]  padded: 17*16B=272B stride
    int t = threadIdx.x;
    int rowBase = blockIdx.x * 128;
    int p = blockIdx.y;
    const float* W = Wall + p * HDIM * HDIM;

#pragma unroll
    for (int q = 0; q < 4; q++) {
        int idx = t + q * 256;
        int c = idx >> 4, k = idx & 15;
        *((float4*)&wst[c][k]) = __ldg(((const float4*)W) + c * 16 + k);
    }
#pragma unroll
    for (int q = 0; q < 8; q++) {
        int idx = t + q * 256;
        int r = idx >> 4, k = idx & 15;
        int gr = rowBase + r;
        float4 v = make_float4(0.f, 0.f, 0.f, 0.f);
        if (gr < n) v = __ldg(((const float4*)X) + gr * 16 + k);
        *((float4*)&xs[r][k]) = v;
    }
    __syncthreads();

    int rg = t >> 3, cg = t & 7;
    unsigned long long acc[4][8];
#pragma unroll
    for (int i = 0; i < 4; i++)
#pragma unroll
        for (int j = 0; j < 8; j++) acc[i][j] = 0ULL;

#pragma unroll
    for (int k = 0; k < 16; k++) {
        ulonglong2 xv[4], wv[8];
#pragma unroll
        for (int i = 0; i < 4; i++) xv[i] = xs[rg * 4 + i][k];
#pragma unroll
        for (int j = 0; j < 8; j++) wv[j] = wst[cg + 8 * j][k];
#pragma unroll
        for (int i = 0; i < 4; i++)
#pragma unroll
            for (int j = 0; j < 8; j++) {
                fma2(acc[i][j], xv[i].x, wv[j].x);
                fma2(acc[i][j], xv[i].y, wv[j].y);
            }
    }

    float* F = g_fts[p];
#pragma unroll
    for (int i = 0; i < 4; i++) {
        int gr = rowBase + rg * 4 + i;
        if (gr < n) {
#pragma unroll
            for (int j = 0; j < 8; j++)
                F[gr * 64 + cg + 8 * j] = unpack_sum(acc[i][j]);
        }
    }
}

// ===========================================================================
// CSR SpMM, pass1+pass2, all p fused. Gather-only; bias folded in; no atomics.
//   embB[p][r] = bias[p] + sum_{e in row r} fts[p][col]*val
//   embA[p][r] = bias[p] + sum_{e, !mask1[col]} fts[p][col]*val
// 16 lanes per row (one float4 slice each), 16 rows per 256-thread block.
// ===========================================================================
__global__ __launch_bounds__(256) void spmm_dual_all(const float* __restrict__ b, int n)
{
    int rr = blockIdx.x * 16 + (threadIdx.x >> 4);
    int l = threadIdx.x & 15;
    if (rr >= n) return;
    int beg = g_off[rr], end = g_off[rr + 1];

    float4 aA[PNUM], aB[PNUM];
#pragma unroll
    for (int p = 0; p < PNUM; p++) {
        float4 bias = __ldg(((const float4*)(b + p * HDIM)) + l);
        aA[p] = bias; aB[p] = bias;
    }
#pragma unroll 2
    for (int i = beg; i < end; i++) {
        int c = __ldg(g_cole + i);
        float v = __ldg(g_vale + i);
        int m = __ldg(g_mflags + i);
        float4 f[PNUM];
#pragma unroll
        for (int p = 0; p < PNUM; p++) {
            f[p] = __ldg(((const float4*)g_fts[p]) + c * 16 + l);
            f[p].x *= v; f[p].y *= v; f[p].z *= v; f[p].w *= v;
            aB[p].x += f[p].x; aB[p].y += f[p].y; aB[p].z += f[p].z; aB[p].w += f[p].w;
        }
        if (!(m & 1)) {
#pragma unroll
            for (int p = 0; p < PNUM; p++) {
                aA[p].x += f[p].x; aA[p].y += f[p].y; aA[p].z += f[p].z; aA[p].w += f[p].w;
            }
        }
    }
#pragma unroll
    for (int p = 0; p < PNUM; p++) {
        ((float4*)g_embA[p])[rr * 16 + l] = aA[p];
        ((float4*)g_embB[p])[rr * 16 + l] = aB[p];
    }
}

// Pass-3: only unmasked (mask2) edges contribute; skip gather entirely otherwise.
__global__ __launch_bounds__(256) void spmm_mask_all(const float* __restrict__ b, int n)
{
    int rr = blockIdx.x * 16 + (threadIdx.x >> 4);
    int l = threadIdx.x & 15;
    if (rr >= n) return;
    int beg = g_off[rr], end = g_off[rr + 1];

    float4 aA[PNUM];
#pragma unroll
    for (int p = 0; p < PNUM; p++)
        aA[p] = __ldg(((const float4*)(b + p * HDIM)) + l);

#pragma unroll 2
    for (int i = beg; i < end; i++) {
        int m = __ldg(g_mflags + i);
        if (m & 2) continue;
        int c = __ldg(g_cole + i);
        float v = __ldg(g_vale + i);
#pragma unroll
        for (int p = 0; p < PNUM; p++) {
            float4 f = __ldg(((const float4*)g_fts[p]) + c * 16 + l);
            aA[p].x += f.x * v; aA[p].y += f.y * v; aA[p].z += f.z * v; aA[p].w += f.w * v;
        }
    }
#pragma unroll
    for (int p = 0; p < PNUM; p++)
        ((float4*)g_embA[p])[rr * 16 + l] = aA[p];
}

// ===========================================================================
// Attention GEMM (all p, all sel in one launch):
//   t[n][j] = tanh(sum_k prelu(emb[n][k]) * fcw[j][k] + fcb[j]); colsum -> g_s
// ===========================================================================
__global__ __launch_bounds__(256) void att_gemm_all(
    const float* __restrict__ a,
    const float* __restrict__ fcw, const float* __restrict__ fcb, int n)
{
    __shared__ ulonglong2 xs[128][16];
    __shared__ ulonglong2 wst[64][17];
    int t = threadIdx.x;
    int rowBase = blockIdx.x * 128;
    int p = blockIdx.y;
    int sel = blockIdx.z;
    float sa = __ldg(a + p);
    const float* E = (sel == 0) ? g_embA[p] : g_embB[p];

#pragma unroll
    for (int q = 0; q < 4; q++) {
        int idx = t + q * 256;
        int c = idx >> 4, k = idx & 15;
        *((float4*)&wst[c][k]) = __ldg(((const float4*)fcw) + c * 16 + k);
    }
#pragma unroll
    for (int q = 0; q < 8; q++) {
        int idx = t + q * 256;
        int r = idx >> 4, k = idx & 15;
        int gr = rowBase + r;
        float4 v = make_float4(0.f, 0.f, 0.f, 0.f);
        if (gr < n) {
            v = __ldg(((const float4*)E) + gr * 16 + k);
            v.x = prelu_f(v.x, sa); v.y = prelu_f(v.y, sa);
            v.z = prelu_f(v.z, sa); v.w = prelu_f(v.w, sa);
        }
        *((float4*)&xs[r][k]) = v;
    }
    __syncthreads();

    int rg = t >> 3, cg = t & 7;
    unsigned long long acc[4][8];
#pragma unroll
    for (int i = 0; i < 4; i++)
#pragma unroll
        for (int j = 0; j < 8; j++) acc[i][j] = 0ULL;

#pragma unroll
    for (int k = 0; k < 16; k++) {
        ulonglong2 xv[4], wv[8];
#pragma unroll
        for (int i = 0; i < 4; i++) xv[i] = xs[rg * 4 + i][k];
#pragma unroll
        for (int j = 0; j < 8; j++) wv[j] = wst[cg + 8 * j][k];
#pragma unroll
        for (int i = 0; i < 4; i++)
#pragma unroll
            for (int j = 0; j < 8; j++) {
                fma2(acc[i][j], xv[i].x, wv[j].x);
                fma2(acc[i][j], xv[i].y, wv[j].y);
            }
    }

    float colsum[8];
#pragma unroll
    for (int j = 0; j < 8; j++) colsum[j] = 0.f;
#pragma unroll
    for (int i = 0; i < 4; i++) {
        int gr = rowBase + rg * 4 + i;
        if (gr < n) {
#pragma unroll
            for (int j = 0; j < 8; j++)
                colsum[j] += tanhf(unpack_sum(acc[i][j]) + __ldg(fcb + cg + 8 * j));
        }
    }
#pragma unroll
    for (int j = 0; j < 8; j++) {
        colsum[j] += __shfl_xor_sync(0xffffffffu, colsum[j], 8);
        colsum[j] += __shfl_xor_sync(0xffffffffu, colsum[j], 16);
    }
    __syncthreads();
    float* ssum = reinterpret_cast<float*>(xs);
    if (t < 64) ssum[t] = 0.f;
    __syncthreads();
    if ((t & 31) < 8) {
#pragma unroll
        for (int j = 0; j < 8; j++) atomicAdd(&ssum[cg + 8 * j], colsum[j]);
    }
    __syncthreads();
    if (t < 64) atomicAdd(&g_s[sel][p * 64 + t], ssum[t]);
}

// ===========================================================================
__global__ void zero_s_k(int both)
{
    int t = threadIdx.x;
    if (t < PNUM * HDIM) {
        g_s[0][t] = 0.f;
        if (both) g_s[1][t] = 0.f;
    }
}

__global__ void softmax_k(int both, const float* __restrict__ att, int n)
{
    __shared__ float lg[2][PNUM];
    int t = threadIdx.x;
    int w = t >> 5, l = t & 31;
    int sel = w / PNUM, p = w % PNUM;
    if (w < PNUM * (both ? 2 : 1)) {
        float v = g_s[sel][p * 64 + l] * __ldg(att + l)
                + g_s[sel][p * 64 + 32 + l] * __ldg(att + 32 + l);
#pragma unroll
        for (int o = 16; o; o >>= 1) v += __shfl_down_sync(0xffffffffu, v, o);
        if (l == 0) lg[sel][p] = v / (float)n;
    }
    __syncthreads();
    if (t < (both ? 2 : 1)) {
        int s = t;
        float m = fmaxf(lg[s][0], fmaxf(lg[s][1], lg[s][2]));
        float e0 = expf(lg[s][0] - m), e1 = expf(lg[s][1] - m), e2 = expf(lg[s][2] - m);
        float inv = 1.f / (e0 + e1 + e2);
        g_beta[s][0] = e0 * inv; g_beta[s][1] = e1 * inv; g_beta[s][2] = e2 * inv;
    }
}

__device__ __forceinline__ float4 comb3(float4 e0, float4 e1, float4 e2,
                                        float b0, float b1, float b2,
                                        float s0, float s1, float s2)
{
    float4 o;
    o.x = b0 * prelu_f(e0.x, s0) + b1 * prelu_f(e1.x, s1) + b2 * prelu_f(e2.x, s2);
    o.y = b0 * prelu_f(e0.y, s0) + b1 * prelu_f(e1.y, s1) + b2 * prelu_f(e2.y, s2);
    o.z = b0 * prelu_f(e0.z, s0) + b1 * prelu_f(e1.z, s1) + b2 * prelu_f(e2.z, s2);
    o.w = b0 * prelu_f(e0.w, s0) + b1 * prelu_f(e1.w, s1) + b2 * prelu_f(e2.w, s2);
    return o;
}

// pass1+2: writes z_mp (from embA, beta[0]) and z_mp2 (from embB, beta[1])
__global__ void combine12_k(const float* __restrict__ a,
                            float* __restrict__ z1, float* __restrict__ z2, int n)
{
    int idx = blockIdx.x * blockDim.x + threadIdx.x;
    if (idx >= n * 16) return;
    float s0 = __ldg(a), s1 = __ldg(a + 1), s2 = __ldg(a + 2);
    float4 a0 = ((const float4*)g_embA[0])[idx];
    float4 a1 = ((const float4*)g_embA[1])[idx];
    float4 a2 = ((const float4*)g_embA[2])[idx];
    ((float4*)z1)[idx] = comb3(a0, a1, a2, g_beta[0][0], g_beta[0][1], g_beta[0][2], s0, s1, s2);
    float4 b0 = ((const float4*)g_embB[0])[idx];
    float4 b1 = ((const float4*)g_embB[1])[idx];
    float4 b2 = ((const float4*)g_embB[2])[idx];
    ((float4*)z2)[idx] = comb3(b0, b1, b2, g_beta[1][0], g_beta[1][1], g_beta[1][2], s0, s1, s2);
}

__global__ void combine3_k(const float* __restrict__ a, float* __restrict__ out, int n)
{
    int idx = blockIdx.x * blockDim.x + threadIdx.x;
    if (idx >= n * 16) return;
    float s0 = __ldg(a), s1 = __ldg(a + 1), s2 = __ldg(a + 2);
    float4 e0 = ((const float4*)g_embA[0])[idx];
    float4 e1 = ((const float4*)g_embA[1])[idx];
    float4 e2 = ((const float4*)g_embA[2])[idx];
    ((float4*)out)[idx] = comb3(e0, e1, e2, g_beta[0][0], g_beta[0][1], g_beta[0][2], s0, s1, s2);
}

// ===========================================================================
extern "C" void kernel_launch(void* const* d_in, const int* in_sizes, int n_in,
                              void* d_out, int out_size)
{
    const float* h     = (const float*)d_in[0];
    const float* W     = (const float*)d_in[1];
    const float* b     = (const float*)d_in[2];
    const float* a     = (const float*)d_in[3];
    const float* fcw   = (const float*)d_in[4];
    const float* fcb   = (const float*)d_in[5];
    const float* att   = (const float*)d_in[6];
    const float* adj   = (const float*)d_in[7];
    const int*   row   = (const int*)d_in[8];
    const int*   col   = (const int*)d_in[9];
    const int*   mask1 = (const int*)d_in[10];
    const int*   mask2 = (const int*)d_in[11];

    int n = in_sizes[0] / HDIM;
    int e = in_sizes[7];

    float* out   = (float*)d_out;
    float* z_mp  = out;
    float* z_mp2 = out + (size_t)n * HDIM;
    float* x_rec = out + (size_t)2 * n * HDIM;

    int gGemm = (n + 127) / 128;
    int gEW   = (n * 16 + 255) / 256;
    int gSp   = (n + 15) / 16;
    int gE    = (e + 255) / 256;
    int gN    = (n + 255) / 256;

    // ---- CSR build (amortized over all 9 SpMMs) ----
    csr_zero<<<gN, 256>>>(n);
    csr_hist<<<gE, 256>>>(row, e);
    csr_scan<<<1, 1024>>>(n);
    csr_scatter<<<gE, 256>>>(row, col, adj, mask1, mask2, e);

    // ---- pass 1 + pass 2 (shared fts = h @ W[p]^T) ----
    zero_s_k<<<1, 256>>>(1);
    gemm_gcn_all<<<dim3(gGemm, PNUM), 256>>>(h, W, n);
    spmm_dual_all<<<gSp, 256>>>(b, n);
    att_gemm_all<<<dim3(gGemm, PNUM, 2), 256>>>(a, fcw, fcb, n);
    softmax_k<<<1, 224>>>(1, att, n);
    combine12_k<<<gEW, 256>>>(a, z_mp, z_mp2, n);

    // ---- pass 3 (decode): input z_mp, mask2 applied at gather side ----
    zero_s_k<<<1, 256>>>(0);
    gemm_gcn_all<<<dim3(gGemm, PNUM), 256>>>(z_mp, W, n);
    spmm_mask_all<<<gSp, 256>>>(b, n);
    att_gemm_all<<<dim3(gGemm, PNUM, 1), 256>>>(a, fcw, fcb, n);
    softmax_k<<<1, 224>>>(0, att, n);
    combine3_k<<<gEW, 256>>>(a, x_rec, n);
}

// round 4
// speedup vs baseline: 1.8725x; 1.0496x over previous
#include <cuda_runtime.h>
#include <cuda_fp16.h>
#include <stdint.h>
#include <math.h>

// Problem constants: N=100000, H=64, E=1600000, P=3
#define NMAX 100000
#define EMAX 1600000
#define HDIM 64
#define PNUM 3

// ---------------- scratch (no allocation allowed -> device globals) -------
__device__ __align__(16) __half g_fts16[PNUM][NMAX * HDIM];   // 38.4 MB (L2-resident)
__device__ __align__(16) float g_embA[PNUM][NMAX * HDIM];     // pass1 / pass3
__device__ __align__(16) float g_embB[PNUM][NMAX * HDIM];     // pass2
__device__ float g_s[2][PNUM * HDIM];
__device__ float g_beta[2][PNUM];

// CSR scratch
__device__ int  g_deg[NMAX];
__device__ int  g_off[NMAX + 1];
__device__ int  g_cur[NMAX];
__device__ __align__(16) int2 g_edge[EMAX];   // .x = col | m1<<30 | m2<<31, .y = val bits

__device__ __forceinline__ float prelu_f(float x, float s) { return x > 0.f ? x : s * x; }

// packed f32x2 FMA: d.lo += a.lo*b.lo ; d.hi += a.hi*b.hi
__device__ __forceinline__ void fma2(unsigned long long& d,
                                     unsigned long long a, unsigned long long b)
{
    asm("fma.rn.f32x2 %0, %1, %2, %3;" : "=l"(d) : "l"(a), "l"(b), "l"(d));
}
__device__ __forceinline__ float unpack_sum(unsigned long long v)
{
    float lo, hi;
    asm("mov.b64 {%0,%1}, %2;" : "=f"(lo), "=f"(hi) : "l"(v));
    return lo + hi;
}

// ===========================================================================
// CSR build
// ===========================================================================
__global__ void csr_zero(int n)
{
    int i = blockIdx.x * blockDim.x + threadIdx.x;
    if (i < n) g_deg[i] = 0;
}
__global__ void csr_hist(const int* __restrict__ row, int e)
{
    int i = blockIdx.x * blockDim.x + threadIdx.x;
    if (i < e) atomicAdd(&g_deg[row[i]], 1);
}
__global__ void csr_scan(int n)
{
    __shared__ int part[1024];
    int tid = threadIdx.x;
    int chunk = (n + 1023) >> 10;
    int beg = tid * chunk;
    int end = min(beg + chunk, n);
    int s = 0;
    for (int i = beg; i < end; i++) s += g_deg[i];
    part[tid] = s;
    __syncthreads();
    for (int o = 1; o < 1024; o <<= 1) {
        int t2 = (tid >= o) ? part[tid - o] : 0;
        __syncthreads();
        part[tid] += t2;
        __syncthreads();
    }
    int run = part[tid] - s;
    for (int i = beg; i < end; i++) {
        g_off[i] = run; g_cur[i] = run;
        run += g_deg[i];
    }
    if (tid == 1023) g_off[n] = part[1023];
}
__global__ void csr_scatter(const int* __restrict__ row, const int* __restrict__ col,
                            const float* __restrict__ vals,
                            const int* __restrict__ mask1, const int* __restrict__ mask2,
                            int e)
{
    int i = blockIdx.x * blockDim.x + threadIdx.x;
    if (i >= e) return;
    int r = __ldg(row + i), c = __ldg(col + i);
    float v = __ldg(vals + i);
    int fl = c | (__ldg(mask1 + c) ? (1 << 30) : 0) | (__ldg(mask2 + c) ? (1u << 31) : 0);
    int pos = atomicAdd(&g_cur[r], 1);
    g_edge[pos] = make_int2(fl, __float_as_int(v));
}

// ===========================================================================
// GCN GEMM (ALL p in one block; X tile loaded once):
//   g_fts16[p][n][j] = (half) sum_k X[n][k] * W[p][j][k]
// 128x64 tile, 256 thr, 4x8 thread tile, packed f32x2 FMA.
// ===========================================================================
__global__ __launch_bounds__(256) void gemm_gcn_all3(
    const float* __restrict__ X, const float* __restrict__ Wall, int n)
{
    __shared__ ulonglong2 xs[128][16];   // [row][k4]
    __shared__ ulonglong2 wst[64][17];   // [col][k4], padded stride
    int t = threadIdx.x;
    int rowBase = blockIdx.x * 128;

    // X tile (loaded ONCE, reused for all 3 metapaths)
#pragma unroll
    for (int q = 0; q < 8; q++) {
        int idx = t + q * 256;
        int r = idx >> 4, k = idx & 15;
        int gr = rowBase + r;
        float4 v = make_float4(0.f, 0.f, 0.f, 0.f);
        if (gr < n) v = __ldg(((const float4*)X) + gr * 16 + k);
        *((float4*)&xs[r][k]) = v;
    }

    int rg = t >> 3, cg = t & 7;

    for (int p = 0; p < PNUM; p++) {
        const float* W = Wall + p * HDIM * HDIM;
        if (p) __syncthreads();           // previous compute done before overwriting wst
#pragma unroll
        for (int q = 0; q < 4; q++) {
            int idx = t + q * 256;
            int c = idx >> 4, k = idx & 15;
            *((float4*)&wst[c][k]) = __ldg(((const float4*)W) + c * 16 + k);
        }
        __syncthreads();

        unsigned long long acc[4][8];
#pragma unroll
        for (int i = 0; i < 4; i++)
#pragma unroll
            for (int j = 0; j < 8; j++) acc[i][j] = 0ULL;

#pragma unroll
        for (int k = 0; k < 16; k++) {
            ulonglong2 xv[4], wv[8];
#pragma unroll
            for (int i = 0; i < 4; i++) xv[i] = xs[rg * 4 + i][k];
#pragma unroll
            for (int j = 0; j < 8; j++) wv[j] = wst[cg + 8 * j][k];
#pragma unroll
            for (int i = 0; i < 4; i++)
#pragma unroll
                for (int j = 0; j < 8; j++) {
                    fma2(acc[i][j], xv[i].x, wv[j].x);
                    fma2(acc[i][j], xv[i].y, wv[j].y);
                }
        }

        __half* F = g_fts16[p];
#pragma unroll
        for (int i = 0; i < 4; i++) {
            int gr = rowBase + rg * 4 + i;
            if (gr < n) {
#pragma unroll
                for (int j = 0; j < 8; j++)
                    F[gr * 64 + cg + 8 * j] = __float2half(unpack_sum(acc[i][j]));
            }
        }
    }
}

// ===========================================================================
// CSR SpMM, pass1+pass2, all p fused. fp16 gathers, fp32 accumulate.
// 16 lanes per row, each lane owns 4 columns (8B of the 128B fp16 row).
// ===========================================================================
__device__ __forceinline__ void acc_half4(float4& a, uint2 u, float v)
{
    float2 f01 = __half22float2(*(const __half2*)&u.x);
    float2 f23 = __half22float2(*(const __half2*)&u.y);
    a.x += f01.x * v; a.y += f01.y * v; a.z += f23.x * v; a.w += f23.y * v;
}

__global__ __launch_bounds__(256) void spmm_dual_all(const float* __restrict__ b, int n)
{
    int rr = blockIdx.x * 16 + (threadIdx.x >> 4);
    int l = threadIdx.x & 15;
    if (rr >= n) return;
    int beg = g_off[rr], end = g_off[rr + 1];

    float4 aA[PNUM], aB[PNUM];
#pragma unroll
    for (int p = 0; p < PNUM; p++) {
        float4 bias = __ldg(((const float4*)(b + p * HDIM)) + l);
        aA[p] = bias; aB[p] = bias;
    }
#pragma unroll 4
    for (int i = beg; i < end; i++) {
        int2 ed = __ldg(g_edge + i);
        int c = ed.x & 0xFFFFFF;
        float v = __int_as_float(ed.y);
        bool m1 = (ed.x & (1 << 30)) != 0;
        uint2 u[PNUM];
#pragma unroll
        for (int p = 0; p < PNUM; p++)
            u[p] = __ldg(((const uint2*)g_fts16[p]) + c * 16 + l);
        float4 f[PNUM];
#pragma unroll
        for (int p = 0; p < PNUM; p++) {
            f[p] = make_float4(0.f, 0.f, 0.f, 0.f);
            acc_half4(f[p], u[p], v);
            aB[p].x += f[p].x; aB[p].y += f[p].y; aB[p].z += f[p].z; aB[p].w += f[p].w;
        }
        if (!m1) {
#pragma unroll
            for (int p = 0; p < PNUM; p++) {
                aA[p].x += f[p].x; aA[p].y += f[p].y; aA[p].z += f[p].z; aA[p].w += f[p].w;
            }
        }
    }
#pragma unroll
    for (int p = 0; p < PNUM; p++) {
        ((float4*)g_embA[p])[rr * 16 + l] = aA[p];
        ((float4*)g_embB[p])[rr * 16 + l] = aB[p];
    }
}

// Pass-3: only edges with !mask2[col] contribute; skip gather otherwise.
__global__ __launch_bounds__(256) void spmm_mask_all(const float* __restrict__ b, int n)
{
    int rr = blockIdx.x * 16 + (threadIdx.x >> 4);
    int l = threadIdx.x & 15;
    if (rr >= n) return;
    int beg = g_off[rr], end = g_off[rr + 1];

    float4 aA[PNUM];
#pragma unroll
    for (int p = 0; p < PNUM; p++)
        aA[p] = __ldg(((const float4*)(b + p * HDIM)) + l);

#pragma unroll 4
    for (int i = beg; i < end; i++) {
        int2 ed = __ldg(g_edge + i);
        if (ed.x & (1u << 31)) continue;
        int c = ed.x & 0xFFFFFF;
        float v = __int_as_float(ed.y);
#pragma unroll
        for (int p = 0; p < PNUM; p++) {
            uint2 u = __ldg(((const uint2*)g_fts16[p]) + c * 16 + l);
            acc_half4(aA[p], u, v);
        }
    }
#pragma unroll
    for (int p = 0; p < PNUM; p++)
        ((float4*)g_embA[p])[rr * 16 + l] = aA[p];
}

// ===========================================================================
// Attention GEMM (all p, all sel in one launch)
// ===========================================================================
__global__ __launch_bounds__(256) void att_gemm_all(
    const float* __restrict__ a,
    const float* __restrict__ fcw, const float* __restrict__ fcb, int n)
{
    __shared__ ulonglong2 xs[128][16];
    __shared__ ulonglong2 wst[64][17];
    int t = threadIdx.x;
    int rowBase = blockIdx.x * 128;
    int p = blockIdx.y;
    int sel = blockIdx.z;
    float sa = __ldg(a + p);
    const float* E = (sel == 0) ? g_embA[p] : g_embB[p];

#pragma unroll
    for (int q = 0; q < 4; q++) {
        int idx = t + q * 256;
        int c = idx >> 4, k = idx & 15;
        *((float4*)&wst[c][k]) = __ldg(((const float4*)fcw) + c * 16 + k);
    }
#pragma unroll
    for (int q = 0; q < 8; q++) {
        int idx = t + q * 256;
        int r = idx >> 4, k = idx & 15;
        int gr = rowBase + r;
        float4 v = make_float4(0.f, 0.f, 0.f, 0.f);
        if (gr < n) {
            v = __ldg(((const float4*)E) + gr * 16 + k);
            v.x = prelu_f(v.x, sa); v.y = prelu_f(v.y, sa);
            v.z = prelu_f(v.z, sa); v.w = prelu_f(v.w, sa);
        }
        *((float4*)&xs[r][k]) = v;
    }
    __syncthreads();

    int rg = t >> 3, cg = t & 7;
    unsigned long long acc[4][8];
#pragma unroll
    for (int i = 0; i < 4; i++)
#pragma unroll
        for (int j = 0; j < 8; j++) acc[i][j] = 0ULL;

#pragma unroll
    for (int k = 0; k < 16; k++) {
        ulonglong2 xv[4], wv[8];
#pragma unroll
        for (int i = 0; i < 4; i++) xv[i] = xs[rg * 4 + i][k];
#pragma unroll
        for (int j = 0; j < 8; j++) wv[j] = wst[cg + 8 * j][k];
#pragma unroll
        for (int i = 0; i < 4; i++)
#pragma unroll
            for (int j = 0; j < 8; j++) {
                fma2(acc[i][j], xv[i].x, wv[j].x);
                fma2(acc[i][j], xv[i].y, wv[j].y);
            }
    }

    float colsum[8];
#pragma unroll
    for (int j = 0; j < 8; j++) colsum[j] = 0.f;
#pragma unroll
    for (int i = 0; i < 4; i++) {
        int gr = rowBase + rg * 4 + i;
        if (gr < n) {
#pragma unroll
            for (int j = 0; j < 8; j++)
                colsum[j] += tanhf(unpack_sum(acc[i][j]) + __ldg(fcb + cg + 8 * j));
        }
    }
#pragma unroll
    for (int j = 0; j < 8; j++) {
        colsum[j] += __shfl_xor_sync(0xffffffffu, colsum[j], 8);
        colsum[j] += __shfl_xor_sync(0xffffffffu, colsum[j], 16);
    }
    __syncthreads();
    float* ssum = reinterpret_cast<float*>(xs);
    if (t < 64) ssum[t] = 0.f;
    __syncthreads();
    if ((t & 31) < 8) {
#pragma unroll
        for (int j = 0; j < 8; j++) atomicAdd(&ssum[cg + 8 * j], colsum[j]);
    }
    __syncthreads();
    if (t < 64) atomicAdd(&g_s[sel][p * 64 + t], ssum[t]);
}

// ===========================================================================
__global__ void zero_s_k(int both)
{
    int t = threadIdx.x;
    if (t < PNUM * HDIM) {
        g_s[0][t] = 0.f;
        if (both) g_s[1][t] = 0.f;
    }
}

__global__ void softmax_k(int both, const float* __restrict__ att, int n)
{
    __shared__ float lg[2][PNUM];
    int t = threadIdx.x;
    int w = t >> 5, l = t & 31;
    int sel = w / PNUM, p = w % PNUM;
    if (w < PNUM * (both ? 2 : 1)) {
        float v = g_s[sel][p * 64 + l] * __ldg(att + l)
                + g_s[sel][p * 64 + 32 + l] * __ldg(att + 32 + l);
#pragma unroll
        for (int o = 16; o; o >>= 1) v += __shfl_down_sync(0xffffffffu, v, o);
        if (l == 0) lg[sel][p] = v / (float)n;
    }
    __syncthreads();
    if (t < (both ? 2 : 1)) {
        int s = t;
        float m = fmaxf(lg[s][0], fmaxf(lg[s][1], lg[s][2]));
        float e0 = expf(lg[s][0] - m), e1 = expf(lg[s][1] - m), e2 = expf(lg[s][2] - m);
        float inv = 1.f / (e0 + e1 + e2);
        g_beta[s][0] = e0 * inv; g_beta[s][1] = e1 * inv; g_beta[s][2] = e2 * inv;
    }
}

__device__ __forceinline__ float4 comb3(float4 e0, float4 e1, float4 e2,
                                        float b0, float b1, float b2,
                                        float s0, float s1, float s2)
{
    float4 o;
    o.x = b0 * prelu_f(e0.x, s0) + b1 * prelu_f(e1.x, s1) + b2 * prelu_f(e2.x, s2);
    o.y = b0 * prelu_f(e0.y, s0) + b1 * prelu_f(e1.y, s1) + b2 * prelu_f(e2.y, s2);
    o.z = b0 * prelu_f(e0.z, s0) + b1 * prelu_f(e1.z, s1) + b2 * prelu_f(e2.z, s2);
    o.w = b0 * prelu_f(e0.w, s0) + b1 * prelu_f(e1.w, s1) + b2 * prelu_f(e2.w, s2);
    return o;
}

__global__ void combine12_k(const float* __restrict__ a,
                            float* __restrict__ z1, float* __restrict__ z2, int n)
{
    int idx = blockIdx.x * blockDim.x + threadIdx.x;
    if (idx >= n * 16) return;
    float s0 = __ldg(a), s1 = __ldg(a + 1), s2 = __ldg(a + 2);
    float4 a0 = ((const float4*)g_embA[0])[idx];
    float4 a1 = ((const float4*)g_embA[1])[idx];
    float4 a2 = ((const float4*)g_embA[2])[idx];
    ((float4*)z1)[idx] = comb3(a0, a1, a2, g_beta[0][0], g_beta[0][1], g_beta[0][2], s0, s1, s2);
    float4 b0 = ((const float4*)g_embB[0])[idx];
    float4 b1 = ((const float4*)g_embB[1])[idx];
    float4 b2 = ((const float4*)g_embB[2])[idx];
    ((float4*)z2)[idx] = comb3(b0, b1, b2, g_beta[1][0], g_beta[1][1], g_beta[1][2], s0, s1, s2);
}

__global__ void combine3_k(const float* __restrict__ a, float* __restrict__ out, int n)
{
    int idx = blockIdx.x * blockDim.x + threadIdx.x;
    if (idx >= n * 16) return;
    float s0 = __ldg(a), s1 = __ldg(a + 1), s2 = __ldg(a + 2);
    float4 e0 = ((const float4*)g_embA[0])[idx];
    float4 e1 = ((const float4*)g_embA[1])[idx];
    float4 e2 = ((const float4*)g_embA[2])[idx];
    ((float4*)out)[idx] = comb3(e0, e1, e2, g_beta[0][0], g_beta[0][1], g_beta[0][2], s0, s1, s2);
}

// ===========================================================================
extern "C" void kernel_launch(void* const* d_in, const int* in_sizes, int n_in,
                              void* d_out, int out_size)
{
    const float* h     = (const float*)d_in[0];
    const float* W     = (const float*)d_in[1];
    const float* b     = (const float*)d_in[2];
    const float* a     = (const float*)d_in[3];
    const float* fcw   = (const float*)d_in[4];
    const float* fcb   = (const float*)d_in[5];
    const float* att   = (const float*)d_in[6];
    const float* adj   = (const float*)d_in[7];
    const int*   row   = (const int*)d_in[8];
    const int*   col   = (const int*)d_in[9];
    const int*   mask1 = (const int*)d_in[10];
    const int*   mask2 = (const int*)d_in[11];

    int n = in_sizes[0] / HDIM;
    int e = in_sizes[7];

    float* out   = (float*)d_out;
    float* z_mp  = out;
    float* z_mp2 = out + (size_t)n * HDIM;
    float* x_rec = out + (size_t)2 * n * HDIM;

    int gGemm = (n + 127) / 128;
    int gEW   = (n * 16 + 255) / 256;
    int gSp   = (n + 15) / 16;
    int gE    = (e + 255) / 256;
    int gN    = (n + 255) / 256;

    // ---- CSR build (amortized over all 9 SpMMs) ----
    csr_zero<<<gN, 256>>>(n);
    csr_hist<<<gE, 256>>>(row, e);
    csr_scan<<<1, 1024>>>(n);
    csr_scatter<<<gE, 256>>>(row, col, adj, mask1, mask2, e);

    // ---- pass 1 + pass 2 (shared fts = h @ W[p]^T, fp16) ----
    zero_s_k<<<1, 256>>>(1);
    gemm_gcn_all3<<<gGemm, 256>>>(h, W, n);
    spmm_dual_all<<<gSp, 256>>>(b, n);
    att_gemm_all<<<dim3(gGemm, PNUM, 2), 256>>>(a, fcw, fcb, n);
    softmax_k<<<1, 224>>>(1, att, n);
    combine12_k<<<gEW, 256>>>(a, z_mp, z_mp2, n);

    // ---- pass 3 (decode): input z_mp, mask2 applied at gather side ----
    zero_s_k<<<1, 256>>>(0);
    gemm_gcn_all3<<<gGemm, 256>>>(z_mp, W, n);
    spmm_mask_all<<<gSp, 256>>>(b, n);
    att_gemm_all<<<dim3(gGemm, PNUM, 1), 256>>>(a, fcw, fcb, n);
    softmax_k<<<1, 224>>>(0, att, n);
    combine3_k<<<gEW, 256>>>(a, x_rec, n);
}

// round 7
// speedup vs baseline: 2.6490x; 1.4147x over previous
#include <cuda_runtime.h>
#include <cuda_fp16.h>
#include <stdint.h>
#include <math.h>

// Problem constants: N=100000, H=64, E=1600000, P=3
#define NMAX 100000
#define EMAX 1600000
#define HDIM 64
#define PNUM 3

// ---------------- scratch (no allocation allowed -> device globals) -------
__device__ __align__(16) __half g_fts16[PNUM][NMAX * HDIM];   // 38.4 MB
__device__ __align__(16) float g_embA[PNUM][NMAX * HDIM];     // pass1 / pass3
__device__ __align__(16) float g_embB[PNUM][NMAX * HDIM];     // pass2
__device__ float g_s[2][PNUM * HDIM];
__device__ float g_beta[2][PNUM];

// CSR scratch
__device__ int  g_deg[NMAX];
__device__ int  g_off[NMAX + 1];
__device__ int  g_cur[NMAX];
__device__ __align__(16) int2 g_edge[EMAX];   // .x = col | m1<<30 | m2<<31, .y = val bits

__device__ __forceinline__ float prelu_f(float x, float s) { return x > 0.f ? x : s * x; }

__device__ __forceinline__ uint32_t h2_bits(__half2 h)
{
    return *reinterpret_cast<uint32_t*>(&h);
}

// m16n8k16 row.col HMMA, fp16 inputs, fp32 accumulate (baseline PTX, sm_80+)
__device__ __forceinline__ void mma_16816(float* c, const uint32_t* a, const uint32_t* b)
{
    asm volatile("mma.sync.aligned.m16n8k16.row.col.f32.f16.f16.f32 "
                 "{%0,%1,%2,%3}, {%4,%5,%6,%7}, {%8,%9}, {%0,%1,%2,%3};"
                 : "+f"(c[0]), "+f"(c[1]), "+f"(c[2]), "+f"(c[3])
                 : "r"(a[0]), "r"(a[1]), "r"(a[2]), "r"(a[3]), "r"(b[0]), "r"(b[1]));
}

#define APAD 72   // padded half-stride: bank = (4g+q)%32, conflict-free frags

// ===========================================================================
// CSR build
// ===========================================================================
__global__ void csr_zero(int n)
{
    int i = blockIdx.x * blockDim.x + threadIdx.x;
    if (i < n) g_deg[i] = 0;
}
__global__ void csr_hist(const int* __restrict__ row, int e)
{
    int i = blockIdx.x * blockDim.x + threadIdx.x;
    if (i < e) atomicAdd(&g_deg[row[i]], 1);
}
__global__ void csr_scan(int n)
{
    __shared__ int part[1024];
    int tid = threadIdx.x;
    int chunk = (n + 1023) >> 10;
    int beg = tid * chunk;
    int end = min(beg + chunk, n);
    int s = 0;
    for (int i = beg; i < end; i++) s += g_deg[i];
    part[tid] = s;
    __syncthreads();
    for (int o = 1; o < 1024; o <<= 1) {
        int t2 = (tid >= o) ? part[tid - o] : 0;
        __syncthreads();
        part[tid] += t2;
        __syncthreads();
    }
    int run = part[tid] - s;
    for (int i = beg; i < end; i++) {
        g_off[i] = run; g_cur[i] = run;
        run += g_deg[i];
    }
    if (tid == 1023) g_off[n] = part[1023];
}
__global__ void csr_scatter(const int* __restrict__ row, const int* __restrict__ col,
                            const float* __restrict__ vals,
                            const int* __restrict__ mask1, const int* __restrict__ mask2,
                            int e)
{
    int i = blockIdx.x * blockDim.x + threadIdx.x;
    if (i >= e) return;
    int r = __ldg(row + i), c = __ldg(col + i);
    float v = __ldg(vals + i);
    int fl = c | (__ldg(mask1 + c) ? (1 << 30) : 0) | (__ldg(mask2 + c) ? (1u << 31) : 0);
    int pos = atomicAdd(&g_cur[r], 1);
    g_edge[pos] = make_int2(fl, __float_as_int(v));
}

// ===========================================================================
// GCN GEMM via HMMA: per 128-row tile, loop p:
//   g_fts16[p][m][j] = (half) sum_k X[m][k] * W[p][j][k]
// 4 warps x (2 Mtiles x 8 Ntiles x 4 Ksteps) m16n8k16.
// ===========================================================================
__global__ __launch_bounds__(128) void gemm_gcn_mma(
    const float* __restrict__ X, const float* __restrict__ Wall, int n)
{
    __shared__ __half smA[128 * APAD];
    __shared__ __half smB[64 * APAD];

    int t = threadIdx.x, wid = t >> 5, lane = t & 31;
    int g = lane >> 2, q = lane & 3;
    int rowBase = blockIdx.x * 128;

    // A = X[tile] -> fp16 padded smem (loaded once, reused for all p)
#pragma unroll
    for (int i = 0; i < 16; i++) {
        int idx = t + i * 128;
        int r = idx >> 4, k4 = idx & 15;
        int gr = rowBase + r;
        float4 v = make_float4(0.f, 0.f, 0.f, 0.f);
        if (gr < n) v = __ldg(((const float4*)X) + gr * 16 + k4);
        __half* dst = &smA[r * APAD + k4 * 4];
        *(__half2*)(dst)     = __floats2half2_rn(v.x, v.y);
        *(__half2*)(dst + 2) = __floats2half2_rn(v.z, v.w);
    }

    for (int p = 0; p < PNUM; p++) {
        __syncthreads();   // previous iteration's MMA reads done (and A ready, 1st iter)
        // B = W[p] (64x64 row-major j,k) -> fp16 padded smem
#pragma unroll
        for (int i = 0; i < 8; i++) {
            int idx = t + i * 128;
            int r = idx >> 4, k4 = idx & 15;
            float4 v = __ldg(((const float4*)(Wall + p * 4096)) + r * 16 + k4);
            __half* dst = &smB[r * APAD + k4 * 4];
            *(__half2*)(dst)     = __floats2half2_rn(v.x, v.y);
            *(__half2*)(dst + 2) = __floats2half2_rn(v.z, v.w);
        }
        __syncthreads();

        float acc[2][8][4];
#pragma unroll
        for (int mt = 0; mt < 2; mt++)
#pragma unroll
            for (int nt = 0; nt < 8; nt++)
#pragma unroll
                for (int c = 0; c < 4; c++) acc[mt][nt][c] = 0.f;

#pragma unroll
        for (int ks = 0; ks < 4; ks++) {
            uint32_t afr[2][4];
#pragma unroll
            for (int mt = 0; mt < 2; mt++) {
                int r0 = wid * 32 + mt * 16 + g;
                int kb = ks * 16 + q * 2;
                afr[mt][0] = *(const uint32_t*)&smA[r0 * APAD + kb];
                afr[mt][1] = *(const uint32_t*)&smA[(r0 + 8) * APAD + kb];
                afr[mt][2] = *(const uint32_t*)&smA[r0 * APAD + kb + 8];
                afr[mt][3] = *(const uint32_t*)&smA[(r0 + 8) * APAD + kb + 8];
            }
#pragma unroll
            for (int nt = 0; nt < 8; nt++) {
                int cb = (nt * 8 + g) * APAD + ks * 16 + q * 2;
                uint32_t bfr[2];
                bfr[0] = *(const uint32_t*)&smB[cb];
                bfr[1] = *(const uint32_t*)&smB[cb + 8];
                mma_16816(acc[0][nt], afr[0], bfr);
                mma_16816(acc[1][nt], afr[1], bfr);
            }
        }

        // epilogue: fp16 store (c0,c1)->row, (c2,c3)->row+8
        __half* F = g_fts16[p];
#pragma unroll
        for (int mt = 0; mt < 2; mt++) {
            int r0 = rowBase + wid * 32 + mt * 16 + g;
#pragma unroll
            for (int nt = 0; nt < 8; nt++) {
                int col = nt * 8 + q * 2;
                if (r0 < n)
                    *(__half2*)(F + (size_t)r0 * 64 + col) =
                        __floats2half2_rn(acc[mt][nt][0], acc[mt][nt][1]);
                if (r0 + 8 < n)
                    *(__half2*)(F + (size_t)(r0 + 8) * 64 + col) =
                        __floats2half2_rn(acc[mt][nt][2], acc[mt][nt][3]);
            }
        }
    }
}

// ===========================================================================
// Attention GEMM via HMMA: t[m][j] = tanh(prelu(emb[m]) @ fcw^T + fcb[j]);
// column sums -> g_s[sel][p*64+j]. grid = (tiles, p, sel)
// ===========================================================================
__global__ __launch_bounds__(128) void att_gemm_mma(
    const float* __restrict__ a,
    const float* __restrict__ fcw, const float* __restrict__ fcb, int n)
{
    __shared__ __half smA[128 * APAD];
    __shared__ __half smB[64 * APAD];
    __shared__ float ssum[64];

    int t = threadIdx.x, wid = t >> 5, lane = t & 31;
    int g = lane >> 2, q = lane & 3;
    int rowBase = blockIdx.x * 128;
    int p = blockIdx.y, sel = blockIdx.z;
    float sa = __ldg(a + p);
    const float* E = (sel == 0) ? g_embA[p] : g_embB[p];

    if (t < 64) ssum[t] = 0.f;

    // A = prelu(emb tile) -> fp16
#pragma unroll
    for (int i = 0; i < 16; i++) {
        int idx = t + i * 128;
        int r = idx >> 4, k4 = idx & 15;
        int gr = rowBase + r;
        float4 v = make_float4(0.f, 0.f, 0.f, 0.f);
        if (gr < n) {
            v = __ldg(((const float4*)E) + gr * 16 + k4);
            v.x = prelu_f(v.x, sa); v.y = prelu_f(v.y, sa);
            v.z = prelu_f(v.z, sa); v.w = prelu_f(v.w, sa);
        }
        __half* dst = &smA[r * APAD + k4 * 4];
        *(__half2*)(dst)     = __floats2half2_rn(v.x, v.y);
        *(__half2*)(dst + 2) = __floats2half2_rn(v.z, v.w);
    }
    // B = fcw
#pragma unroll
    for (int i = 0; i < 8; i++) {
        int idx = t + i * 128;
        int r = idx >> 4, k4 = idx & 15;
        float4 v = __ldg(((const float4*)fcw) + r * 16 + k4);
        __half* dst = &smB[r * APAD + k4 * 4];
        *(__half2*)(dst)     = __floats2half2_rn(v.x, v.y);
        *(__half2*)(dst + 2) = __floats2half2_rn(v.z, v.w);
    }
    __syncthreads();

    float acc[2][8][4];
#pragma unroll
    for (int mt = 0; mt < 2; mt++)
#pragma unroll
        for (int nt = 0; nt < 8; nt++)
#pragma unroll
            for (int c = 0; c < 4; c++) acc[mt][nt][c] = 0.f;

#pragma unroll
    for (int ks = 0; ks < 4; ks++) {
        uint32_t afr[2][4];
#pragma unroll
        for (int mt = 0; mt < 2; mt++) {
            int r0 = wid * 32 + mt * 16 + g;
            int kb = ks * 16 + q * 2;
            afr[mt][0] = *(const uint32_t*)&smA[r0 * APAD + kb];
            afr[mt][1] = *(const uint32_t*)&smA[(r0 + 8) * APAD + kb];
            afr[mt][2] = *(const uint32_t*)&smA[r0 * APAD + kb + 8];
            afr[mt][3] = *(const uint32_t*)&smA[(r0 + 8) * APAD + kb + 8];
        }
#pragma unroll
        for (int nt = 0; nt < 8; nt++) {
            int cb = (nt * 8 + g) * APAD + ks * 16 + q * 2;
            uint32_t bfr[2];
            bfr[0] = *(const uint32_t*)&smB[cb];
            bfr[1] = *(const uint32_t*)&smB[cb + 8];
            mma_16816(acc[0][nt], afr[0], bfr);
            mma_16816(acc[1][nt], afr[1], bfr);
        }
    }

    // epilogue: tanh(c + fcb) and column sums.
    // thread owns cols {nt*8+q*2, nt*8+q*2+1}; rows g, g+8 per mtile.
    float colsum[16];
#pragma unroll
    for (int i = 0; i < 16; i++) colsum[i] = 0.f;
#pragma unroll
    for (int mt = 0; mt < 2; mt++) {
        int r0 = rowBase + wid * 32 + mt * 16 + g;
#pragma unroll
        for (int nt = 0; nt < 8; nt++) {
            int col = nt * 8 + q * 2;
            float fb0 = __ldg(fcb + col), fb1 = __ldg(fcb + col + 1);
            if (r0 < n) {
                colsum[nt * 2]     += tanhf(acc[mt][nt][0] + fb0);
                colsum[nt * 2 + 1] += tanhf(acc[mt][nt][1] + fb1);
            }
            if (r0 + 8 < n) {
                colsum[nt * 2]     += tanhf(acc[mt][nt][2] + fb0);
                colsum[nt * 2 + 1] += tanhf(acc[mt][nt][3] + fb1);
            }
        }
    }
    // reduce across g (lanes 4,8,16 apart share q -> same column set)
#pragma unroll
    for (int o = 4; o < 32; o <<= 1) {
#pragma unroll
        for (int i = 0; i < 16; i++)
            colsum[i] += __shfl_xor_sync(0xffffffffu, colsum[i], o);
    }
    if (lane < 4) {
#pragma unroll
        for (int nt = 0; nt < 8; nt++) {
            atomicAdd(&ssum[nt * 8 + q * 2], colsum[nt * 2]);
            atomicAdd(&ssum[nt * 8 + q * 2 + 1], colsum[nt * 2 + 1]);
        }
    }
    __syncthreads();
    if (t < 64) atomicAdd(&g_s[sel][p * 64 + t], ssum[t]);
}

// ===========================================================================
// CSR SpMM, pass1+pass2, all p fused. fp16 gathers, fp32 accumulate.
// ===========================================================================
__device__ __forceinline__ void acc_half4(float4& a, uint2 u, float v)
{
    float2 f01 = __half22float2(*(const __half2*)&u.x);
    float2 f23 = __half22float2(*(const __half2*)&u.y);
    a.x += f01.x * v; a.y += f01.y * v; a.z += f23.x * v; a.w += f23.y * v;
}

__global__ __launch_bounds__(256) void spmm_dual_all(const float* __restrict__ b, int n)
{
    int rr = blockIdx.x * 16 + (threadIdx.x >> 4);
    int l = threadIdx.x & 15;
    if (rr >= n) return;
    int beg = g_off[rr], end = g_off[rr + 1];

    float4 aA[PNUM], aB[PNUM];
#pragma unroll
    for (int p = 0; p < PNUM; p++) {
        float4 bias = __ldg(((const float4*)(b + p * HDIM)) + l);
        aA[p] = bias; aB[p] = bias;
    }
#pragma unroll 4
    for (int i = beg; i < end; i++) {
        int2 ed = __ldg(g_edge + i);
        int c = ed.x & 0xFFFFFF;
        float v = __int_as_float(ed.y);
        bool m1 = (ed.x & (1 << 30)) != 0;
        uint2 u[PNUM];
#pragma unroll
        for (int p = 0; p < PNUM; p++)
            u[p] = __ldg(((const uint2*)g_fts16[p]) + c * 16 + l);
        float4 f[PNUM];
#pragma unroll
        for (int p = 0; p < PNUM; p++) {
            f[p] = make_float4(0.f, 0.f, 0.f, 0.f);
            acc_half4(f[p], u[p], v);
            aB[p].x += f[p].x; aB[p].y += f[p].y; aB[p].z += f[p].z; aB[p].w += f[p].w;
        }
        if (!m1) {
#pragma unroll
            for (int p = 0; p < PNUM; p++) {
                aA[p].x += f[p].x; aA[p].y += f[p].y; aA[p].z += f[p].z; aA[p].w += f[p].w;
            }
        }
    }
#pragma unroll
    for (int p = 0; p < PNUM; p++) {
        ((float4*)g_embA[p])[rr * 16 + l] = aA[p];
        ((float4*)g_embB[p])[rr * 16 + l] = aB[p];
    }
}

__global__ __launch_bounds__(256) void spmm_mask_all(const float* __restrict__ b, int n)
{
    int rr = blockIdx.x * 16 + (threadIdx.x >> 4);
    int l = threadIdx.x & 15;
    if (rr >= n) return;
    int beg = g_off[rr], end = g_off[rr + 1];

    float4 aA[PNUM];
#pragma unroll
    for (int p = 0; p < PNUM; p++)
        aA[p] = __ldg(((const float4*)(b + p * HDIM)) + l);

#pragma unroll 4
    for (int i = beg; i < end; i++) {
        int2 ed = __ldg(g_edge + i);
        if (ed.x & (1u << 31)) continue;
        int c = ed.x & 0xFFFFFF;
        float v = __int_as_float(ed.y);
#pragma unroll
        for (int p = 0; p < PNUM; p++) {
            uint2 u = __ldg(((const uint2*)g_fts16[p]) + c * 16 + l);
            acc_half4(aA[p], u, v);
        }
    }
#pragma unroll
    for (int p = 0; p < PNUM; p++)
        ((float4*)g_embA[p])[rr * 16 + l] = aA[p];
}

// ===========================================================================
__global__ void zero_s_k(int both)
{
    int t = threadIdx.x;
    if (t < PNUM * HDIM) {
        g_s[0][t] = 0.f;
        if (both) g_s[1][t] = 0.f;
    }
}

__global__ void softmax_k(int both, const float* __restrict__ att, int n)
{
    __shared__ float lg[2][PNUM];
    int t = threadIdx.x;
    int w = t >> 5, l = t & 31;
    int sel = w / PNUM, p = w % PNUM;
    if (w < PNUM * (both ? 2 : 1)) {
        float v = g_s[sel][p * 64 + l] * __ldg(att + l)
                + g_s[sel][p * 64 + 32 + l] * __ldg(att + 32 + l);
#pragma unroll
        for (int o = 16; o; o >>= 1) v += __shfl_down_sync(0xffffffffu, v, o);
        if (l == 0) lg[sel][p] = v / (float)n;
    }
    __syncthreads();
    if (t < (both ? 2 : 1)) {
        int s = t;
        float m = fmaxf(lg[s][0], fmaxf(lg[s][1], lg[s][2]));
        float e0 = expf(lg[s][0] - m), e1 = expf(lg[s][1] - m), e2 = expf(lg[s][2] - m);
        float inv = 1.f / (e0 + e1 + e2);
        g_beta[s][0] = e0 * inv; g_beta[s][1] = e1 * inv; g_beta[s][2] = e2 * inv;
    }
}

__device__ __forceinline__ float4 comb3(float4 e0, float4 e1, float4 e2,
                                        float b0, float b1, float b2,
                                        float s0, float s1, float s2)
{
    float4 o;
    o.x = b0 * prelu_f(e0.x, s0) + b1 * prelu_f(e1.x, s1) + b2 * prelu_f(e2.x, s2);
    o.y = b0 * prelu_f(e0.y, s0) + b1 * prelu_f(e1.y, s1) + b2 * prelu_f(e2.y, s2);
    o.z = b0 * prelu_f(e0.z, s0) + b1 * prelu_f(e1.z, s1) + b2 * prelu_f(e2.z, s2);
    o.w = b0 * prelu_f(e0.w, s0) + b1 * prelu_f(e1.w, s1) + b2 * prelu_f(e2.w, s2);
    return o;
}

__global__ void combine12_k(const float* __restrict__ a,
                            float* __restrict__ z1, float* __restrict__ z2, int n)
{
    int idx = blockIdx.x * blockDim.x + threadIdx.x;
    if (idx >= n * 16) return;
    float s0 = __ldg(a), s1 = __ldg(a + 1), s2 = __ldg(a + 2);
    float4 a0 = ((const float4*)g_embA[0])[idx];
    float4 a1 = ((const float4*)g_embA[1])[idx];
    float4 a2 = ((const float4*)g_embA[2])[idx];
    ((float4*)z1)[idx] = comb3(a0, a1, a2, g_beta[0][0], g_beta[0][1], g_beta[0][2], s0, s1, s2);
    float4 b0 = ((const float4*)g_embB[0])[idx];
    float4 b1 = ((const float4*)g_embB[1])[idx];
    float4 b2 = ((const float4*)g_embB[2])[idx];
    ((float4*)z2)[idx] = comb3(b0, b1, b2, g_beta[1][0], g_beta[1][1], g_beta[1][2], s0, s1, s2);
}

__global__ void combine3_k(const float* __restrict__ a, float* __restrict__ out, int n)
{
    int idx = blockIdx.x * blockDim.x + threadIdx.x;
    if (idx >= n * 16) return;
    float s0 = __ldg(a), s1 = __ldg(a + 1), s2 = __ldg(a + 2);
    float4 e0 = ((const float4*)g_embA[0])[idx];
    float4 e1 = ((const float4*)g_embA[1])[idx];
    float4 e2 = ((const float4*)g_embA[2])[idx];
    ((float4*)out)[idx] = comb3(e0, e1, e2, g_beta[0][0], g_beta[0][1], g_beta[0][2], s0, s1, s2);
}

// ===========================================================================
extern "C" void kernel_launch(void* const* d_in, const int* in_sizes, int n_in,
                              void* d_out, int out_size)
{
    const float* h     = (const float*)d_in[0];
    const float* W     = (const float*)d_in[1];
    const float* b     = (const float*)d_in[2];
    const float* a     = (const float*)d_in[3];
    const float* fcw   = (const float*)d_in[4];
    const float* fcb   = (const float*)d_in[5];
    const float* att   = (const float*)d_in[6];
    const float* adj   = (const float*)d_in[7];
    const int*   row   = (const int*)d_in[8];
    const int*   col   = (const int*)d_in[9];
    const int*   mask1 = (const int*)d_in[10];
    const int*   mask2 = (const int*)d_in[11];

    int n = in_sizes[0] / HDIM;
    int e = in_sizes[7];

    float* out   = (float*)d_out;
    float* z_mp  = out;
    float* z_mp2 = out + (size_t)n * HDIM;
    float* x_rec = out + (size_t)2 * n * HDIM;

    int gGemm = (n + 127) / 128;
    int gEW   = (n * 16 + 255) / 256;
    int gSp   = (n + 15) / 16;
    int gE    = (e + 255) / 256;
    int gN    = (n + 255) / 256;

    // ---- CSR build (amortized over all 9 SpMMs) ----
    csr_zero<<<gN, 256>>>(n);
    csr_hist<<<gE, 256>>>(row, e);
    csr_scan<<<1, 1024>>>(n);
    csr_scatter<<<gE, 256>>>(row, col, adj, mask1, mask2, e);

    // ---- pass 1 + pass 2 (shared fts = h @ W[p]^T, fp16, HMMA) ----
    zero_s_k<<<1, 256>>>(1);
    gemm_gcn_mma<<<gGemm, 128>>>(h, W, n);
    spmm_dual_all<<<gSp, 256>>>(b, n);
    att_gemm_mma<<<dim3(gGemm, PNUM, 2), 128>>>(a, fcw, fcb, n);
    softmax_k<<<1, 224>>>(1, att, n);
    combine12_k<<<gEW, 256>>>(a, z_mp, z_mp2, n);

    // ---- pass 3 (decode): input z_mp, mask2 applied at gather side ----
    zero_s_k<<<1, 256>>>(0);
    gemm_gcn_mma<<<gGemm, 128>>>(z_mp, W, n);
    spmm_mask_all<<<gSp, 256>>>(b, n);
    att_gemm_mma<<<dim3(gGemm, PNUM, 1), 128>>>(a, fcw, fcb, n);
    softmax_k<<<1, 224>>>(0, att, n);
    combine3_k<<<gEW, 256>>>(a, x_rec, n);
}

// round 8
// speedup vs baseline: 2.8788x; 1.0867x over previous
#include <cuda_runtime.h>
#include <cuda_fp16.h>
#include <stdint.h>
#include <math.h>

// Problem constants: N=100000, H=64, E=1600000, P=3
#define NMAX 100000
#define EMAX 1600000
#define HDIM 64
#define PNUM 3

// ---------------- scratch (no allocation allowed -> device globals) -------
__device__ __align__(16) __half g_fts16[PNUM][NMAX * HDIM];   // 38.4 MB
__device__ __align__(16) __half g_embA[PNUM][NMAX * HDIM];    // 19.2 MB (fp16 now)
__device__ __align__(16) __half g_embB[PNUM][NMAX * HDIM];    // 19.2 MB
__device__ float g_s[2][PNUM * HDIM];
__device__ float g_beta[2][PNUM];

// CSR scratch
__device__ int  g_deg[NMAX];
__device__ int  g_off[NMAX + 1];
__device__ int  g_cur[NMAX];
__device__ __align__(16) int2 g_edge[EMAX];   // .x = col | m1<<30 | m2<<31, .y = val bits

__device__ __forceinline__ float prelu_f(float x, float s) { return x > 0.f ? x : s * x; }

__device__ __forceinline__ uint32_t h2_bits(__half2 h)
{
    return *reinterpret_cast<uint32_t*>(&h);
}

// m16n8k16 row.col HMMA, fp16 inputs, fp32 accumulate
__device__ __forceinline__ void mma_16816(float* c, const uint32_t* a, const uint32_t* b)
{
    asm volatile("mma.sync.aligned.m16n8k16.row.col.f32.f16.f16.f32 "
                 "{%0,%1,%2,%3}, {%4,%5,%6,%7}, {%8,%9}, {%0,%1,%2,%3};"
                 : "+f"(c[0]), "+f"(c[1]), "+f"(c[2]), "+f"(c[3])
                 : "r"(a[0]), "r"(a[1]), "r"(a[2]), "r"(a[3]), "r"(b[0]), "r"(b[1]));
}

#define APAD 72   // padded half-stride: conflict-free 4B fragment loads

// ===========================================================================
// CSR build
// ===========================================================================
__global__ void csr_zero(int n)
{
    int i = blockIdx.x * blockDim.x + threadIdx.x;
    if (i < n) g_deg[i] = 0;
}
__global__ void csr_hist(const int* __restrict__ row, int e)
{
    int i = blockIdx.x * blockDim.x + threadIdx.x;
    if (i < e) atomicAdd(&g_deg[row[i]], 1);
}
__global__ void csr_scan(int n)
{
    __shared__ int part[1024];
    int tid = threadIdx.x;
    int chunk = (n + 1023) >> 10;
    int beg = tid * chunk;
    int end = min(beg + chunk, n);
    int s = 0;
    for (int i = beg; i < end; i++) s += g_deg[i];
    part[tid] = s;
    __syncthreads();
    for (int o = 1; o < 1024; o <<= 1) {
        int t2 = (tid >= o) ? part[tid - o] : 0;
        __syncthreads();
        part[tid] += t2;
        __syncthreads();
    }
    int run = part[tid] - s;
    for (int i = beg; i < end; i++) {
        g_off[i] = run; g_cur[i] = run;
        run += g_deg[i];
    }
    if (tid == 1023) g_off[n] = part[1023];
}
__global__ void csr_scatter(const int* __restrict__ row, const int* __restrict__ col,
                            const float* __restrict__ vals,
                            const int* __restrict__ mask1, const int* __restrict__ mask2,
                            int e)
{
    int i = blockIdx.x * blockDim.x + threadIdx.x;
    if (i >= e) return;
    int r = __ldg(row + i), c = __ldg(col + i);
    float v = __ldg(vals + i);
    int fl = c | (__ldg(mask1 + c) ? (1 << 30) : 0) | (__ldg(mask2 + c) ? (1u << 31) : 0);
    int pos = atomicAdd(&g_cur[r], 1);
    g_edge[pos] = make_int2(fl, __float_as_int(v));
}

// ===========================================================================
// GCN GEMM via HMMA: per 128-row tile, loop p:
//   g_fts16[p][m][j] = (half) sum_k X[m][k] * W[p][j][k]
// ===========================================================================
__global__ __launch_bounds__(128) void gemm_gcn_mma(
    const float* __restrict__ X, const float* __restrict__ Wall, int n)
{
    __shared__ __half smA[128 * APAD];
    __shared__ __half smB[64 * APAD];

    int t = threadIdx.x, wid = t >> 5, lane = t & 31;
    int g = lane >> 2, q = lane & 3;
    int rowBase = blockIdx.x * 128;

#pragma unroll
    for (int i = 0; i < 16; i++) {
        int idx = t + i * 128;
        int r = idx >> 4, k4 = idx & 15;
        int gr = rowBase + r;
        float4 v = make_float4(0.f, 0.f, 0.f, 0.f);
        if (gr < n) v = __ldg(((const float4*)X) + gr * 16 + k4);
        __half* dst = &smA[r * APAD + k4 * 4];
        *(__half2*)(dst)     = __floats2half2_rn(v.x, v.y);
        *(__half2*)(dst + 2) = __floats2half2_rn(v.z, v.w);
    }

    for (int p = 0; p < PNUM; p++) {
        __syncthreads();
#pragma unroll
        for (int i = 0; i < 8; i++) {
            int idx = t + i * 128;
            int r = idx >> 4, k4 = idx & 15;
            float4 v = __ldg(((const float4*)(Wall + p * 4096)) + r * 16 + k4);
            __half* dst = &smB[r * APAD + k4 * 4];
            *(__half2*)(dst)     = __floats2half2_rn(v.x, v.y);
            *(__half2*)(dst + 2) = __floats2half2_rn(v.z, v.w);
        }
        __syncthreads();

        float acc[2][8][4];
#pragma unroll
        for (int mt = 0; mt < 2; mt++)
#pragma unroll
            for (int nt = 0; nt < 8; nt++)
#pragma unroll
                for (int c = 0; c < 4; c++) acc[mt][nt][c] = 0.f;

#pragma unroll
        for (int ks = 0; ks < 4; ks++) {
            uint32_t afr[2][4];
#pragma unroll
            for (int mt = 0; mt < 2; mt++) {
                int r0 = wid * 32 + mt * 16 + g;
                int kb = ks * 16 + q * 2;
                afr[mt][0] = *(const uint32_t*)&smA[r0 * APAD + kb];
                afr[mt][1] = *(const uint32_t*)&smA[(r0 + 8) * APAD + kb];
                afr[mt][2] = *(const uint32_t*)&smA[r0 * APAD + kb + 8];
                afr[mt][3] = *(const uint32_t*)&smA[(r0 + 8) * APAD + kb + 8];
            }
#pragma unroll
            for (int nt = 0; nt < 8; nt++) {
                int cb = (nt * 8 + g) * APAD + ks * 16 + q * 2;
                uint32_t bfr[2];
                bfr[0] = *(const uint32_t*)&smB[cb];
                bfr[1] = *(const uint32_t*)&smB[cb + 8];
                mma_16816(acc[0][nt], afr[0], bfr);
                mma_16816(acc[1][nt], afr[1], bfr);
            }
        }

        __half* F = g_fts16[p];
#pragma unroll
        for (int mt = 0; mt < 2; mt++) {
            int r0 = rowBase + wid * 32 + mt * 16 + g;
#pragma unroll
            for (int nt = 0; nt < 8; nt++) {
                int col = nt * 8 + q * 2;
                if (r0 < n)
                    *(__half2*)(F + (size_t)r0 * 64 + col) =
                        __floats2half2_rn(acc[mt][nt][0], acc[mt][nt][1]);
                if (r0 + 8 < n)
                    *(__half2*)(F + (size_t)(r0 + 8) * 64 + col) =
                        __floats2half2_rn(acc[mt][nt][2], acc[mt][nt][3]);
            }
        }
    }
}

// ===========================================================================
// Attention GEMM via HMMA (fp16 emb input): grid = (tiles, p), sel as arg
// ===========================================================================
__global__ __launch_bounds__(128) void att_gemm_mma(
    int sel, const float* __restrict__ a,
    const float* __restrict__ fcw, const float* __restrict__ fcb, int n)
{
    __shared__ __half smA[128 * APAD];
    __shared__ __half smB[64 * APAD];
    __shared__ float ssum[64];

    int t = threadIdx.x, wid = t >> 5, lane = t & 31;
    int g = lane >> 2, q = lane & 3;
    int rowBase = blockIdx.x * 128;
    int p = blockIdx.y;
    float sa = __ldg(a + p);
    const __half* E = (sel == 0) ? g_embA[p] : g_embB[p];

    if (t < 64) ssum[t] = 0.f;

    // A = prelu(emb tile fp16) -> fp16
#pragma unroll
    for (int i = 0; i < 16; i++) {
        int idx = t + i * 128;
        int r = idx >> 4, k4 = idx & 15;
        int gr = rowBase + r;
        float4 v = make_float4(0.f, 0.f, 0.f, 0.f);
        if (gr < n) {
            uint2 u = *((const uint2*)(E + (size_t)gr * 64 + k4 * 4));
            float2 f01 = __half22float2(*(__half2*)&u.x);
            float2 f23 = __half22float2(*(__half2*)&u.y);
            v.x = prelu_f(f01.x, sa); v.y = prelu_f(f01.y, sa);
            v.z = prelu_f(f23.x, sa); v.w = prelu_f(f23.y, sa);
        }
        __half* dst = &smA[r * APAD + k4 * 4];
        *(__half2*)(dst)     = __floats2half2_rn(v.x, v.y);
        *(__half2*)(dst + 2) = __floats2half2_rn(v.z, v.w);
    }
#pragma unroll
    for (int i = 0; i < 8; i++) {
        int idx = t + i * 128;
        int r = idx >> 4, k4 = idx & 15;
        float4 v = __ldg(((const float4*)fcw) + r * 16 + k4);
        __half* dst = &smB[r * APAD + k4 * 4];
        *(__half2*)(dst)     = __floats2half2_rn(v.x, v.y);
        *(__half2*)(dst + 2) = __floats2half2_rn(v.z, v.w);
    }
    __syncthreads();

    float acc[2][8][4];
#pragma unroll
    for (int mt = 0; mt < 2; mt++)
#pragma unroll
        for (int nt = 0; nt < 8; nt++)
#pragma unroll
            for (int c = 0; c < 4; c++) acc[mt][nt][c] = 0.f;

#pragma unroll
    for (int ks = 0; ks < 4; ks++) {
        uint32_t afr[2][4];
#pragma unroll
        for (int mt = 0; mt < 2; mt++) {
            int r0 = wid * 32 + mt * 16 + g;
            int kb = ks * 16 + q * 2;
            afr[mt][0] = *(const uint32_t*)&smA[r0 * APAD + kb];
            afr[mt][1] = *(const uint32_t*)&smA[(r0 + 8) * APAD + kb];
            afr[mt][2] = *(const uint32_t*)&smA[r0 * APAD + kb + 8];
            afr[mt][3] = *(const uint32_t*)&smA[(r0 + 8) * APAD + kb + 8];
        }
#pragma unroll
        for (int nt = 0; nt < 8; nt++) {
            int cb = (nt * 8 + g) * APAD + ks * 16 + q * 2;
            uint32_t bfr[2];
            bfr[0] = *(const uint32_t*)&smB[cb];
            bfr[1] = *(const uint32_t*)&smB[cb + 8];
            mma_16816(acc[0][nt], afr[0], bfr);
            mma_16816(acc[1][nt], afr[1], bfr);
        }
    }

    float colsum[16];
#pragma unroll
    for (int i = 0; i < 16; i++) colsum[i] = 0.f;
#pragma unroll
    for (int mt = 0; mt < 2; mt++) {
        int r0 = rowBase + wid * 32 + mt * 16 + g;
#pragma unroll
        for (int nt = 0; nt < 8; nt++) {
            int col = nt * 8 + q * 2;
            float fb0 = __ldg(fcb + col), fb1 = __ldg(fcb + col + 1);
            if (r0 < n) {
                colsum[nt * 2]     += tanhf(acc[mt][nt][0] + fb0);
                colsum[nt * 2 + 1] += tanhf(acc[mt][nt][1] + fb1);
            }
            if (r0 + 8 < n) {
                colsum[nt * 2]     += tanhf(acc[mt][nt][2] + fb0);
                colsum[nt * 2 + 1] += tanhf(acc[mt][nt][3] + fb1);
            }
        }
    }
#pragma unroll
    for (int o = 4; o < 32; o <<= 1) {
#pragma unroll
        for (int i = 0; i < 16; i++)
            colsum[i] += __shfl_xor_sync(0xffffffffu, colsum[i], o);
    }
    if (lane < 4) {
#pragma unroll
        for (int nt = 0; nt < 8; nt++) {
            atomicAdd(&ssum[nt * 8 + q * 2], colsum[nt * 2]);
            atomicAdd(&ssum[nt * 8 + q * 2 + 1], colsum[nt * 2 + 1]);
        }
    }
    __syncthreads();
    if (t < 64) atomicAdd(&g_s[sel][p * 64 + t], ssum[t]);
}

// ===========================================================================
// CSR SpMM (fp16 gathers, fp32 accumulate, fp16 emb stores)
// ===========================================================================
__device__ __forceinline__ void acc_half4(float4& a, uint2 u, float v)
{
    float2 f01 = __half22float2(*(const __half2*)&u.x);
    float2 f23 = __half22float2(*(const __half2*)&u.y);
    a.x += f01.x * v; a.y += f01.y * v; a.z += f23.x * v; a.w += f23.y * v;
}
__device__ __forceinline__ uint2 pack_half4(float4 a)
{
    __half2 h0 = __floats2half2_rn(a.x, a.y);
    __half2 h1 = __floats2half2_rn(a.z, a.w);
    return make_uint2(h2_bits(h0), h2_bits(h1));
}

__global__ __launch_bounds__(256) void spmm_dual_all(const float* __restrict__ b, int n)
{
    int rr = blockIdx.x * 16 + (threadIdx.x >> 4);
    int l = threadIdx.x & 15;
    if (rr >= n) return;
    int beg = g_off[rr], end = g_off[rr + 1];

    float4 aA[PNUM], aB[PNUM];
#pragma unroll
    for (int p = 0; p < PNUM; p++) {
        float4 bias = __ldg(((const float4*)(b + p * HDIM)) + l);
        aA[p] = bias; aB[p] = bias;
    }
#pragma unroll 4
    for (int i = beg; i < end; i++) {
        int2 ed = __ldg(g_edge + i);
        int c = ed.x & 0xFFFFFF;
        float v = __int_as_float(ed.y);
        bool m1 = (ed.x & (1 << 30)) != 0;
        uint2 u[PNUM];
#pragma unroll
        for (int p = 0; p < PNUM; p++)
            u[p] = __ldg(((const uint2*)g_fts16[p]) + c * 16 + l);
        float4 f[PNUM];
#pragma unroll
        for (int p = 0; p < PNUM; p++) {
            f[p] = make_float4(0.f, 0.f, 0.f, 0.f);
            acc_half4(f[p], u[p], v);
            aB[p].x += f[p].x; aB[p].y += f[p].y; aB[p].z += f[p].z; aB[p].w += f[p].w;
        }
        if (!m1) {
#pragma unroll
            for (int p = 0; p < PNUM; p++) {
                aA[p].x += f[p].x; aA[p].y += f[p].y; aA[p].z += f[p].z; aA[p].w += f[p].w;
            }
        }
    }
#pragma unroll
    for (int p = 0; p < PNUM; p++) {
        ((uint2*)g_embA[p])[rr * 16 + l] = pack_half4(aA[p]);
        ((uint2*)g_embB[p])[rr * 16 + l] = pack_half4(aB[p]);
    }
}

__global__ __launch_bounds__(256) void spmm_mask_all(const float* __restrict__ b, int n)
{
    int rr = blockIdx.x * 16 + (threadIdx.x >> 4);
    int l = threadIdx.x & 15;
    if (rr >= n) return;
    int beg = g_off[rr], end = g_off[rr + 1];

    float4 aA[PNUM];
#pragma unroll
    for (int p = 0; p < PNUM; p++)
        aA[p] = __ldg(((const float4*)(b + p * HDIM)) + l);

#pragma unroll 4
    for (int i = beg; i < end; i++) {
        int2 ed = __ldg(g_edge + i);
        if (ed.x & (1u << 31)) continue;
        int c = ed.x & 0xFFFFFF;
        float v = __int_as_float(ed.y);
#pragma unroll
        for (int p = 0; p < PNUM; p++) {
            uint2 u = __ldg(((const uint2*)g_fts16[p]) + c * 16 + l);
            acc_half4(aA[p], u, v);
        }
    }
#pragma unroll
    for (int p = 0; p < PNUM; p++)
        ((uint2*)g_embA[p])[rr * 16 + l] = pack_half4(aA[p]);
}

// ===========================================================================
__global__ void zero_s_k(int both)
{
    int t = threadIdx.x;
    if (t < PNUM * HDIM) {
        g_s[0][t] = 0.f;
        if (both) g_s[1][t] = 0.f;
    }
}

// single-sel softmax: 3 warps, one per p
__global__ void softmax1_k(int sel, const float* __restrict__ att, int n)
{
    __shared__ float lg[PNUM];
    int t = threadIdx.x;
    int w = t >> 5, l = t & 31;
    if (w < PNUM) {
        float v = g_s[sel][w * 64 + l] * __ldg(att + l)
                + g_s[sel][w * 64 + 32 + l] * __ldg(att + 32 + l);
#pragma unroll
        for (int o = 16; o; o >>= 1) v += __shfl_down_sync(0xffffffffu, v, o);
        if (l == 0) lg[w] = v / (float)n;
    }
    __syncthreads();
    if (t == 0) {
        float m = fmaxf(lg[0], fmaxf(lg[1], lg[2]));
        float e0 = expf(lg[0] - m), e1 = expf(lg[1] - m), e2 = expf(lg[2] - m);
        float inv = 1.f / (e0 + e1 + e2);
        g_beta[sel][0] = e0 * inv; g_beta[sel][1] = e1 * inv; g_beta[sel][2] = e2 * inv;
    }
}

// combine from fp16 emb: out[n][h] = sum_p beta_p * prelu(emb_p[n][h], a_p)
__global__ void combine_k(int sel, const float* __restrict__ a,
                          float* __restrict__ out, int n)
{
    int idx = blockIdx.x * blockDim.x + threadIdx.x;
    if (idx >= n * 16) return;
    float b0 = g_beta[sel][0], b1 = g_beta[sel][1], b2 = g_beta[sel][2];
    float s0 = __ldg(a), s1 = __ldg(a + 1), s2 = __ldg(a + 2);
    const uint2* E0 = (const uint2*)(sel == 0 ? g_embA[0] : g_embB[0]);
    const uint2* E1 = (const uint2*)(sel == 0 ? g_embA[1] : g_embB[1]);
    const uint2* E2 = (const uint2*)(sel == 0 ? g_embA[2] : g_embB[2]);
    float4 e0 = make_float4(0, 0, 0, 0), e1 = e0, e2 = e0;
    acc_half4(e0, E0[idx], 1.f);
    acc_half4(e1, E1[idx], 1.f);
    acc_half4(e2, E2[idx], 1.f);
    float4 o;
    o.x = b0 * prelu_f(e0.x, s0) + b1 * prelu_f(e1.x, s1) + b2 * prelu_f(e2.x, s2);
    o.y = b0 * prelu_f(e0.y, s0) + b1 * prelu_f(e1.y, s1) + b2 * prelu_f(e2.y, s2);
    o.z = b0 * prelu_f(e0.z, s0) + b1 * prelu_f(e1.z, s1) + b2 * prelu_f(e2.z, s2);
    o.w = b0 * prelu_f(e0.w, s0) + b1 * prelu_f(e1.w, s1) + b2 * prelu_f(e2.w, s2);
    ((float4*)out)[idx] = o;
}

// ===========================================================================
extern "C" void kernel_launch(void* const* d_in, const int* in_sizes, int n_in,
                              void* d_out, int out_size)
{
    const float* h     = (const float*)d_in[0];
    const float* W     = (const float*)d_in[1];
    const float* b     = (const float*)d_in[2];
    const float* a     = (const float*)d_in[3];
    const float* fcw   = (const float*)d_in[4];
    const float* fcb   = (const float*)d_in[5];
    const float* att   = (const float*)d_in[6];
    const float* adj   = (const float*)d_in[7];
    const int*   row   = (const int*)d_in[8];
    const int*   col   = (const int*)d_in[9];
    const int*   mask1 = (const int*)d_in[10];
    const int*   mask2 = (const int*)d_in[11];

    int n = in_sizes[0] / HDIM;
    int e = in_sizes[7];

    float* out   = (float*)d_out;
    float* z_mp  = out;
    float* z_mp2 = out + (size_t)n * HDIM;
    float* x_rec = out + (size_t)2 * n * HDIM;

    int gGemm = (n + 127) / 128;
    int gEW   = (n * 16 + 255) / 256;
    int gSp   = (n + 15) / 16;
    int gE    = (e + 255) / 256;
    int gN    = (n + 255) / 256;

    // one-time infra (created outside capture on the correctness call;
    // identical captured work on every call thereafter)
    static cudaStream_t s2 = nullptr;
    static cudaEvent_t evFork = nullptr, evCsr = nullptr, evSpmm = nullptr, evDone = nullptr;
    if (s2 == nullptr) {
        cudaStreamCreateWithFlags(&s2, cudaStreamNonBlocking);
        cudaEventCreateWithFlags(&evFork, cudaEventDisableTiming);
        cudaEventCreateWithFlags(&evCsr, cudaEventDisableTiming);
        cudaEventCreateWithFlags(&evSpmm, cudaEventDisableTiming);
        cudaEventCreateWithFlags(&evDone, cudaEventDisableTiming);
    }
    cudaStream_t s0 = 0;

    // ---- fork: CSR build on s2, pass-1 GEMM on main (independent) ----
    cudaEventRecord(evFork, s0);
    cudaStreamWaitEvent(s2, evFork, 0);

    csr_zero<<<gN, 256, 0, s2>>>(n);
    csr_hist<<<gE, 256, 0, s2>>>(row, e);
    csr_scan<<<1, 1024, 0, s2>>>(n);
    csr_scatter<<<gE, 256, 0, s2>>>(row, col, adj, mask1, mask2, e);
    cudaEventRecord(evCsr, s2);

    zero_s_k<<<1, 256, 0, s0>>>(1);
    gemm_gcn_mma<<<gGemm, 128, 0, s0>>>(h, W, n);

    // ---- join: SpMM needs CSR + fts ----
    cudaStreamWaitEvent(s0, evCsr, 0);
    spmm_dual_all<<<gSp, 256, 0, s0>>>(b, n);
    cudaEventRecord(evSpmm, s0);

    // ---- branch B on s2: sel=1 chain (z_mp2), independent of pass 3 ----
    cudaStreamWaitEvent(s2, evSpmm, 0);
    att_gemm_mma<<<dim3(gGemm, PNUM), 128, 0, s2>>>(1, a, fcw, fcb, n);
    softmax1_k<<<1, 96, 0, s2>>>(1, att, n);
    combine_k<<<gEW, 256, 0, s2>>>(1, a, z_mp2, n);
    cudaEventRecord(evDone, s2);

    // ---- main chain: sel=0 then pass 3 ----
    att_gemm_mma<<<dim3(gGemm, PNUM), 128, 0, s0>>>(0, a, fcw, fcb, n);
    softmax1_k<<<1, 96, 0, s0>>>(0, att, n);
    combine_k<<<gEW, 256, 0, s0>>>(0, a, z_mp, n);

    zero_s_k<<<1, 256, 0, s0>>>(0);
    gemm_gcn_mma<<<gGemm, 128, 0, s0>>>(z_mp, W, n);
    spmm_mask_all<<<gSp, 256, 0, s0>>>(b, n);
    att_gemm_mma<<<dim3(gGemm, PNUM), 128, 0, s0>>>(0, a, fcw, fcb, n);
    softmax1_k<<<1, 96, 0, s0>>>(0, att, n);
    combine_k<<<gEW, 256, 0, s0>>>(0, a, x_rec, n);

    // ---- final join ----
    cudaStreamWaitEvent(s0, evDone, 0);
}

// round 9
// speedup vs baseline: 3.0183x; 1.0484x over previous
#include <cuda_runtime.h>
#include <cuda_fp16.h>
#include <stdint.h>
#include <math.h>

// Problem constants: N=100000, H=64, E=1600000, P=3
#define NMAX 100000
#define EMAX 1600000
#define HDIM 64
#define PNUM 3

// ---------------- scratch (no allocation allowed -> device globals) -------
__device__ __align__(16) __half g_fts16[PNUM][NMAX * HDIM];   // 38.4 MB
__device__ __align__(16) __half g_embA[PNUM][NMAX * HDIM];    // 19.2 MB
__device__ __align__(16) __half g_embB[PNUM][NMAX * HDIM];    // 19.2 MB
__device__ __align__(16) __half g_z16[NMAX * HDIM];           // 12.8 MB (z_mp fp16)
__device__ float g_s[2][PNUM * HDIM];

// CSR scratch
__device__ int  g_deg[NMAX];
__device__ int  g_off[NMAX + 1];
__device__ int  g_cur[NMAX];
__device__ __align__(16) int2 g_edge[EMAX];   // .x = col | m1<<30 | m2<<31, .y = val bits

__device__ __forceinline__ float prelu_f(float x, float s) { return x > 0.f ? x : s * x; }

__device__ __forceinline__ uint32_t h2_bits(__half2 h)
{
    return *reinterpret_cast<uint32_t*>(&h);
}

// m16n8k16 row.col HMMA, fp16 inputs, fp32 accumulate
__device__ __forceinline__ void mma_16816(float* c, const uint32_t* a, const uint32_t* b)
{
    asm volatile("mma.sync.aligned.m16n8k16.row.col.f32.f16.f16.f32 "
                 "{%0,%1,%2,%3}, {%4,%5,%6,%7}, {%8,%9}, {%0,%1,%2,%3};"
                 : "+f"(c[0]), "+f"(c[1]), "+f"(c[2]), "+f"(c[3])
                 : "r"(a[0]), "r"(a[1]), "r"(a[2]), "r"(a[3]), "r"(b[0]), "r"(b[1]));
}

#define APAD 72   // padded half-stride: conflict-free 4B fragment loads

// ===========================================================================
// CSR build
// ===========================================================================
__global__ void csr_zero(int n)
{
    int i = blockIdx.x * blockDim.x + threadIdx.x;
    if (i < n) g_deg[i] = 0;
}
__global__ void csr_hist(const int* __restrict__ row, int e)
{
    int i = blockIdx.x * blockDim.x + threadIdx.x;
    if (i < e) atomicAdd(&g_deg[row[i]], 1);
}
__global__ void csr_scan(int n)
{
    __shared__ int part[1024];
    int tid = threadIdx.x;
    int chunk = (n + 1023) >> 10;
    int beg = tid * chunk;
    int end = min(beg + chunk, n);
    int s = 0;
    for (int i = beg; i < end; i++) s += g_deg[i];
    part[tid] = s;
    __syncthreads();
    for (int o = 1; o < 1024; o <<= 1) {
        int t2 = (tid >= o) ? part[tid - o] : 0;
        __syncthreads();
        part[tid] += t2;
        __syncthreads();
    }
    int run = part[tid] - s;
    for (int i = beg; i < end; i++) {
        g_off[i] = run; g_cur[i] = run;
        run += g_deg[i];
    }
    if (tid == 1023) g_off[n] = part[1023];
}
__global__ void csr_scatter(const int* __restrict__ row, const int* __restrict__ col,
                            const float* __restrict__ vals,
                            const int* __restrict__ mask1, const int* __restrict__ mask2,
                            int e)
{
    int i = blockIdx.x * blockDim.x + threadIdx.x;
    if (i >= e) return;
    int r = __ldg(row + i), c = __ldg(col + i);
    float v = __ldg(vals + i);
    int fl = c | (__ldg(mask1 + c) ? (1 << 30) : 0) | (__ldg(mask2 + c) ? (1u << 31) : 0);
    int pos = atomicAdd(&g_cur[r], 1);
    g_edge[pos] = make_int2(fl, __float_as_int(v));
}

// ===========================================================================
// GCN GEMM via HMMA (fp32 input): loop p per 128-row tile
// ===========================================================================
__global__ __launch_bounds__(128) void gemm_gcn_mma(
    const float* __restrict__ X, const float* __restrict__ Wall, int n)
{
    __shared__ __half smA[128 * APAD];
    __shared__ __half smB[64 * APAD];

    int t = threadIdx.x, wid = t >> 5, lane = t & 31;
    int g = lane >> 2, q = lane & 3;
    int rowBase = blockIdx.x * 128;

#pragma unroll
    for (int i = 0; i < 16; i++) {
        int idx = t + i * 128;
        int r = idx >> 4, k4 = idx & 15;
        int gr = rowBase + r;
        float4 v = make_float4(0.f, 0.f, 0.f, 0.f);
        if (gr < n) v = __ldg(((const float4*)X) + gr * 16 + k4);
        __half* dst = &smA[r * APAD + k4 * 4];
        *(__half2*)(dst)     = __floats2half2_rn(v.x, v.y);
        *(__half2*)(dst + 2) = __floats2half2_rn(v.z, v.w);
    }

    for (int p = 0; p < PNUM; p++) {
        __syncthreads();
#pragma unroll
        for (int i = 0; i < 8; i++) {
            int idx = t + i * 128;
            int r = idx >> 4, k4 = idx & 15;
            float4 v = __ldg(((const float4*)(Wall + p * 4096)) + r * 16 + k4);
            __half* dst = &smB[r * APAD + k4 * 4];
            *(__half2*)(dst)     = __floats2half2_rn(v.x, v.y);
            *(__half2*)(dst + 2) = __floats2half2_rn(v.z, v.w);
        }
        __syncthreads();

        float acc[2][8][4];
#pragma unroll
        for (int mt = 0; mt < 2; mt++)
#pragma unroll
            for (int nt = 0; nt < 8; nt++)
#pragma unroll
                for (int c = 0; c < 4; c++) acc[mt][nt][c] = 0.f;

#pragma unroll
        for (int ks = 0; ks < 4; ks++) {
            uint32_t afr[2][4];
#pragma unroll
            for (int mt = 0; mt < 2; mt++) {
                int r0 = wid * 32 + mt * 16 + g;
                int kb = ks * 16 + q * 2;
                afr[mt][0] = *(const uint32_t*)&smA[r0 * APAD + kb];
                afr[mt][1] = *(const uint32_t*)&smA[(r0 + 8) * APAD + kb];
                afr[mt][2] = *(const uint32_t*)&smA[r0 * APAD + kb + 8];
                afr[mt][3] = *(const uint32_t*)&smA[(r0 + 8) * APAD + kb + 8];
            }
#pragma unroll
            for (int nt = 0; nt < 8; nt++) {
                int cb = (nt * 8 + g) * APAD + ks * 16 + q * 2;
                uint32_t bfr[2];
                bfr[0] = *(const uint32_t*)&smB[cb];
                bfr[1] = *(const uint32_t*)&smB[cb + 8];
                mma_16816(acc[0][nt], afr[0], bfr);
                mma_16816(acc[1][nt], afr[1], bfr);
            }
        }

        __half* F = g_fts16[p];
#pragma unroll
        for (int mt = 0; mt < 2; mt++) {
            int r0 = rowBase + wid * 32 + mt * 16 + g;
#pragma unroll
            for (int nt = 0; nt < 8; nt++) {
                int col = nt * 8 + q * 2;
                if (r0 < n)
                    *(__half2*)(F + (size_t)r0 * 64 + col) =
                        __floats2half2_rn(acc[mt][nt][0], acc[mt][nt][1]);
                if (r0 + 8 < n)
                    *(__half2*)(F + (size_t)(r0 + 8) * 64 + col) =
                        __floats2half2_rn(acc[mt][nt][2], acc[mt][nt][3]);
            }
        }
    }
}

// fp16-input variant (pass 3: reads g_z16 directly)
__global__ __launch_bounds__(128) void gemm_gcn_mma_h(
    const float* __restrict__ Wall, int n)
{
    __shared__ __half smA[128 * APAD];
    __shared__ __half smB[64 * APAD];

    int t = threadIdx.x, wid = t >> 5, lane = t & 31;
    int g = lane >> 2, q = lane & 3;
    int rowBase = blockIdx.x * 128;

#pragma unroll
    for (int i = 0; i < 16; i++) {
        int idx = t + i * 128;
        int r = idx >> 4, k4 = idx & 15;
        int gr = rowBase + r;
        uint2 u = make_uint2(0u, 0u);
        if (gr < n) u = *((const uint2*)(g_z16 + (size_t)gr * 64 + k4 * 4));
        *(uint2*)&smA[r * APAD + k4 * 4] = u;
    }

    for (int p = 0; p < PNUM; p++) {
        __syncthreads();
#pragma unroll
        for (int i = 0; i < 8; i++) {
            int idx = t + i * 128;
            int r = idx >> 4, k4 = idx & 15;
            float4 v = __ldg(((const float4*)(Wall + p * 4096)) + r * 16 + k4);
            __half* dst = &smB[r * APAD + k4 * 4];
            *(__half2*)(dst)     = __floats2half2_rn(v.x, v.y);
            *(__half2*)(dst + 2) = __floats2half2_rn(v.z, v.w);
        }
        __syncthreads();

        float acc[2][8][4];
#pragma unroll
        for (int mt = 0; mt < 2; mt++)
#pragma unroll
            for (int nt = 0; nt < 8; nt++)
#pragma unroll
                for (int c = 0; c < 4; c++) acc[mt][nt][c] = 0.f;

#pragma unroll
        for (int ks = 0; ks < 4; ks++) {
            uint32_t afr[2][4];
#pragma unroll
            for (int mt = 0; mt < 2; mt++) {
                int r0 = wid * 32 + mt * 16 + g;
                int kb = ks * 16 + q * 2;
                afr[mt][0] = *(const uint32_t*)&smA[r0 * APAD + kb];
                afr[mt][1] = *(const uint32_t*)&smA[(r0 + 8) * APAD + kb];
                afr[mt][2] = *(const uint32_t*)&smA[r0 * APAD + kb + 8];
                afr[mt][3] = *(const uint32_t*)&smA[(r0 + 8) * APAD + kb + 8];
            }
#pragma unroll
            for (int nt = 0; nt < 8; nt++) {
                int cb = (nt * 8 + g) * APAD + ks * 16 + q * 2;
                uint32_t bfr[2];
                bfr[0] = *(const uint32_t*)&smB[cb];
                bfr[1] = *(const uint32_t*)&smB[cb + 8];
                mma_16816(acc[0][nt], afr[0], bfr);
                mma_16816(acc[1][nt], afr[1], bfr);
            }
        }

        __half* F = g_fts16[p];
#pragma unroll
        for (int mt = 0; mt < 2; mt++) {
            int r0 = rowBase + wid * 32 + mt * 16 + g;
#pragma unroll
            for (int nt = 0; nt < 8; nt++) {
                int col = nt * 8 + q * 2;
                if (r0 < n)
                    *(__half2*)(F + (size_t)r0 * 64 + col) =
                        __floats2half2_rn(acc[mt][nt][0], acc[mt][nt][1]);
                if (r0 + 8 < n)
                    *(__half2*)(F + (size_t)(r0 + 8) * 64 + col) =
                        __floats2half2_rn(acc[mt][nt][2], acc[mt][nt][3]);
            }
        }
    }
}

// ===========================================================================
// Attention GEMM via HMMA (fp16 emb input): grid = (tiles, p), sel as arg
// ===========================================================================
__global__ __launch_bounds__(128) void att_gemm_mma(
    int sel, const float* __restrict__ a,
    const float* __restrict__ fcw, const float* __restrict__ fcb, int n)
{
    __shared__ __half smA[128 * APAD];
    __shared__ __half smB[64 * APAD];
    __shared__ float ssum[64];

    int t = threadIdx.x, wid = t >> 5, lane = t & 31;
    int g = lane >> 2, q = lane & 3;
    int rowBase = blockIdx.x * 128;
    int p = blockIdx.y;
    float sa = __ldg(a + p);
    const __half* E = (sel == 0) ? g_embA[p] : g_embB[p];

    if (t < 64) ssum[t] = 0.f;

#pragma unroll
    for (int i = 0; i < 16; i++) {
        int idx = t + i * 128;
        int r = idx >> 4, k4 = idx & 15;
        int gr = rowBase + r;
        float4 v = make_float4(0.f, 0.f, 0.f, 0.f);
        if (gr < n) {
            uint2 u = *((const uint2*)(E + (size_t)gr * 64 + k4 * 4));
            float2 f01 = __half22float2(*(__half2*)&u.x);
            float2 f23 = __half22float2(*(__half2*)&u.y);
            v.x = prelu_f(f01.x, sa); v.y = prelu_f(f01.y, sa);
            v.z = prelu_f(f23.x, sa); v.w = prelu_f(f23.y, sa);
        }
        __half* dst = &smA[r * APAD + k4 * 4];
        *(__half2*)(dst)     = __floats2half2_rn(v.x, v.y);
        *(__half2*)(dst + 2) = __floats2half2_rn(v.z, v.w);
    }
#pragma unroll
    for (int i = 0; i < 8; i++) {
        int idx = t + i * 128;
        int r = idx >> 4, k4 = idx & 15;
        float4 v = __ldg(((const float4*)fcw) + r * 16 + k4);
        __half* dst = &smB[r * APAD + k4 * 4];
        *(__half2*)(dst)     = __floats2half2_rn(v.x, v.y);
        *(__half2*)(dst + 2) = __floats2half2_rn(v.z, v.w);
    }
    __syncthreads();

    float acc[2][8][4];
#pragma unroll
    for (int mt = 0; mt < 2; mt++)
#pragma unroll
        for (int nt = 0; nt < 8; nt++)
#pragma unroll
            for (int c = 0; c < 4; c++) acc[mt][nt][c] = 0.f;

#pragma unroll
    for (int ks = 0; ks < 4; ks++) {
        uint32_t afr[2][4];
#pragma unroll
        for (int mt = 0; mt < 2; mt++) {
            int r0 = wid * 32 + mt * 16 + g;
            int kb = ks * 16 + q * 2;
            afr[mt][0] = *(const uint32_t*)&smA[r0 * APAD + kb];
            afr[mt][1] = *(const uint32_t*)&smA[(r0 + 8) * APAD + kb];
            afr[mt][2] = *(const uint32_t*)&smA[r0 * APAD + kb + 8];
            afr[mt][3] = *(const uint32_t*)&smA[(r0 + 8) * APAD + kb + 8];
        }
#pragma unroll
        for (int nt = 0; nt < 8; nt++) {
            int cb = (nt * 8 + g) * APAD + ks * 16 + q * 2;
            uint32_t bfr[2];
            bfr[0] = *(const uint32_t*)&smB[cb];
            bfr[1] = *(const uint32_t*)&smB[cb + 8];
            mma_16816(acc[0][nt], afr[0], bfr);
            mma_16816(acc[1][nt], afr[1], bfr);
        }
    }

    float colsum[16];
#pragma unroll
    for (int i = 0; i < 16; i++) colsum[i] = 0.f;
#pragma unroll
    for (int mt = 0; mt < 2; mt++) {
        int r0 = rowBase + wid * 32 + mt * 16 + g;
#pragma unroll
        for (int nt = 0; nt < 8; nt++) {
            int col = nt * 8 + q * 2;
            float fb0 = __ldg(fcb + col), fb1 = __ldg(fcb + col + 1);
            if (r0 < n) {
                colsum[nt * 2]     += tanhf(acc[mt][nt][0] + fb0);
                colsum[nt * 2 + 1] += tanhf(acc[mt][nt][1] + fb1);
            }
            if (r0 + 8 < n) {
                colsum[nt * 2]     += tanhf(acc[mt][nt][2] + fb0);
                colsum[nt * 2 + 1] += tanhf(acc[mt][nt][3] + fb1);
            }
        }
    }
#pragma unroll
    for (int o = 4; o < 32; o <<= 1) {
#pragma unroll
        for (int i = 0; i < 16; i++)
            colsum[i] += __shfl_xor_sync(0xffffffffu, colsum[i], o);
    }
    if (lane < 4) {
#pragma unroll
        for (int nt = 0; nt < 8; nt++) {
            atomicAdd(&ssum[nt * 8 + q * 2], colsum[nt * 2]);
            atomicAdd(&ssum[nt * 8 + q * 2 + 1], colsum[nt * 2 + 1]);
        }
    }
    __syncthreads();
    if (t < 64) atomicAdd(&g_s[sel][p * 64 + t], ssum[t]);
}

// ===========================================================================
// CSR SpMM: 4-edge batching, branchless masking, fp16 in/out, fp32 accumulate
// ===========================================================================
__device__ __forceinline__ float4 gath_mul(uint2 u, float v)
{
    float2 f01 = __half22float2(*(const __half2*)&u.x);
    float2 f23 = __half22float2(*(const __half2*)&u.y);
    return make_float4(f01.x * v, f01.y * v, f23.x * v, f23.y * v);
}
__device__ __forceinline__ uint2 pack_half4(float4 a)
{
    __half2 h0 = __floats2half2_rn(a.x, a.y);
    __half2 h1 = __floats2half2_rn(a.z, a.w);
    return make_uint2(h2_bits(h0), h2_bits(h1));
}

__global__ __launch_bounds__(256) void spmm_dual_all(const float* __restrict__ b, int n)
{
    // fold g_s zeroing into block 0 (runs before any att_gemm in stream order)
    if (blockIdx.x == 0 && threadIdx.x < PNUM * HDIM) {
        g_s[0][threadIdx.x] = 0.f;
        g_s[1][threadIdx.x] = 0.f;
    }

    int rr = blockIdx.x * 16 + (threadIdx.x >> 4);
    int l = threadIdx.x & 15;
    if (rr >= n) return;
    int beg = g_off[rr], end = g_off[rr + 1];

    float4 aA[PNUM], aB[PNUM];
#pragma unroll
    for (int p = 0; p < PNUM; p++) {
        float4 bias = __ldg(((const float4*)(b + p * HDIM)) + l);
        aA[p] = bias; aB[p] = bias;
    }

    int i = beg;
#pragma unroll 1
    for (; i + 4 <= end; i += 4) {
        int2 ed[4];
#pragma unroll
        for (int j = 0; j < 4; j++) ed[j] = __ldg(g_edge + i + j);
        uint2 u[4][PNUM];
#pragma unroll
        for (int j = 0; j < 4; j++) {
            int c = ed[j].x & 0xFFFFFF;
#pragma unroll
            for (int p = 0; p < PNUM; p++)
                u[j][p] = __ldg(((const uint2*)g_fts16[p]) + c * 16 + l);
        }
#pragma unroll
        for (int j = 0; j < 4; j++) {
            float v = __int_as_float(ed[j].y);
            float sA = (ed[j].x & (1 << 30)) ? 0.f : 1.f;
#pragma unroll
            for (int p = 0; p < PNUM; p++) {
                float4 f = gath_mul(u[j][p], v);
                aB[p].x += f.x; aB[p].y += f.y; aB[p].z += f.z; aB[p].w += f.w;
                aA[p].x = fmaf(f.x, sA, aA[p].x);
                aA[p].y = fmaf(f.y, sA, aA[p].y);
                aA[p].z = fmaf(f.z, sA, aA[p].z);
                aA[p].w = fmaf(f.w, sA, aA[p].w);
            }
        }
    }
#pragma unroll 1
    for (; i < end; i++) {
        int2 ed = __ldg(g_edge + i);
        int c = ed.x & 0xFFFFFF;
        float v = __int_as_float(ed.y);
        float sA = (ed.x & (1 << 30)) ? 0.f : 1.f;
#pragma unroll
        for (int p = 0; p < PNUM; p++) {
            uint2 u = __ldg(((const uint2*)g_fts16[p]) + c * 16 + l);
            float4 f = gath_mul(u, v);
            aB[p].x += f.x; aB[p].y += f.y; aB[p].z += f.z; aB[p].w += f.w;
            aA[p].x = fmaf(f.x, sA, aA[p].x);
            aA[p].y = fmaf(f.y, sA, aA[p].y);
            aA[p].z = fmaf(f.z, sA, aA[p].z);
            aA[p].w = fmaf(f.w, sA, aA[p].w);
        }
    }
#pragma unroll
    for (int p = 0; p < PNUM; p++) {
        ((uint2*)g_embA[p])[rr * 16 + l] = pack_half4(aA[p]);
        ((uint2*)g_embB[p])[rr * 16 + l] = pack_half4(aB[p]);
    }
}

__global__ __launch_bounds__(256) void spmm_mask_all(const float* __restrict__ b, int n)
{
    if (blockIdx.x == 0 && threadIdx.x < PNUM * HDIM)
        g_s[0][threadIdx.x] = 0.f;

    int rr = blockIdx.x * 16 + (threadIdx.x >> 4);
    int l = threadIdx.x & 15;
    if (rr >= n) return;
    int beg = g_off[rr], end = g_off[rr + 1];

    float4 aA[PNUM];
#pragma unroll
    for (int p = 0; p < PNUM; p++)
        aA[p] = __ldg(((const float4*)(b + p * HDIM)) + l);

    int i = beg;
#pragma unroll 1
    for (; i + 4 <= end; i += 4) {
        int2 ed[4];
#pragma unroll
        for (int j = 0; j < 4; j++) ed[j] = __ldg(g_edge + i + j);
        uint2 u[4][PNUM];
#pragma unroll
        for (int j = 0; j < 4; j++) {
            int c = ed[j].x & 0xFFFFFF;
#pragma unroll
            for (int p = 0; p < PNUM; p++)
                u[j][p] = __ldg(((const uint2*)g_fts16[p]) + c * 16 + l);
        }
#pragma unroll
        for (int j = 0; j < 4; j++) {
            float v = (ed[j].x & (1u << 31)) ? 0.f : __int_as_float(ed[j].y);
#pragma unroll
            for (int p = 0; p < PNUM; p++) {
                float4 f = gath_mul(u[j][p], v);
                aA[p].x += f.x; aA[p].y += f.y; aA[p].z += f.z; aA[p].w += f.w;
            }
        }
    }
#pragma unroll 1
    for (; i < end; i++) {
        int2 ed = __ldg(g_edge + i);
        int c = ed.x & 0xFFFFFF;
        float v = (ed.x & (1u << 31)) ? 0.f : __int_as_float(ed.y);
#pragma unroll
        for (int p = 0; p < PNUM; p++) {
            uint2 u = __ldg(((const uint2*)g_fts16[p]) + c * 16 + l);
            float4 f = gath_mul(u, v);
            aA[p].x += f.x; aA[p].y += f.y; aA[p].z += f.z; aA[p].w += f.w;
        }
    }
#pragma unroll
    for (int p = 0; p < PNUM; p++)
        ((uint2*)g_embA[p])[rr * 16 + l] = pack_half4(aA[p]);
}

// ===========================================================================
// combine: inline softmax(beta) from g_s, then
//   out[n][h] = sum_p beta_p * prelu(emb_p[n][h], a_p)  (+ optional fp16 copy)
// ===========================================================================
__global__ void combine_k(int sel, int writez, const float* __restrict__ a,
                          const float* __restrict__ att, float* __restrict__ out, int n)
{
    __shared__ float sbeta[PNUM];
    int t = threadIdx.x;
    {
        int w = t >> 5, l = t & 31;
        if (w < PNUM) {
            float v = g_s[sel][w * 64 + l] * __ldg(att + l)
                    + g_s[sel][w * 64 + 32 + l] * __ldg(att + 32 + l);
#pragma unroll
            for (int o = 16; o; o >>= 1) v += __shfl_down_sync(0xffffffffu, v, o);
            if (l == 0) sbeta[w] = v / (float)n;
        }
    }
    __syncthreads();
    if (t == 0) {
        float m = fmaxf(sbeta[0], fmaxf(sbeta[1], sbeta[2]));
        float e0 = expf(sbeta[0] - m), e1 = expf(sbeta[1] - m), e2 = expf(sbeta[2] - m);
        float inv = 1.f / (e0 + e1 + e2);
        sbeta[0] = e0 * inv; sbeta[1] = e1 * inv; sbeta[2] = e2 * inv;
    }
    __syncthreads();

    int idx = blockIdx.x * blockDim.x + t;
    if (idx >= n * 16) return;
    float b0 = sbeta[0], b1 = sbeta[1], b2 = sbeta[2];
    float s0 = __ldg(a), s1 = __ldg(a + 1), s2 = __ldg(a + 2);
    const uint2* E0 = (const uint2*)(sel == 0 ? g_embA[0] : g_embB[0]);
    const uint2* E1 = (const uint2*)(sel == 0 ? g_embA[1] : g_embB[1]);
    const uint2* E2 = (const uint2*)(sel == 0 ? g_embA[2] : g_embB[2]);
    float4 e0 = gath_mul(E0[idx], 1.f);
    float4 e1 = gath_mul(E1[idx], 1.f);
    float4 e2 = gath_mul(E2[idx], 1.f);
    float4 o;
    o.x = b0 * prelu_f(e0.x, s0) + b1 * prelu_f(e1.x, s1) + b2 * prelu_f(e2.x, s2);
    o.y = b0 * prelu_f(e0.y, s0) + b1 * prelu_f(e1.y, s1) + b2 * prelu_f(e2.y, s2);
    o.z = b0 * prelu_f(e0.z, s0) + b1 * prelu_f(e1.z, s1) + b2 * prelu_f(e2.z, s2);
    o.w = b0 * prelu_f(e0.w, s0) + b1 * prelu_f(e1.w, s1) + b2 * prelu_f(e2.w, s2);
    ((float4*)out)[idx] = o;
    if (writez) ((uint2*)g_z16)[idx] = pack_half4(o);
}

// ===========================================================================
extern "C" void kernel_launch(void* const* d_in, const int* in_sizes, int n_in,
                              void* d_out, int out_size)
{
    const float* h     = (const float*)d_in[0];
    const float* W     = (const float*)d_in[1];
    const float* b     = (const float*)d_in[2];
    const float* a     = (const float*)d_in[3];
    const float* fcw   = (const float*)d_in[4];
    const float* fcb   = (const float*)d_in[5];
    const float* att   = (const float*)d_in[6];
    const float* adj   = (const float*)d_in[7];
    const int*   row   = (const int*)d_in[8];
    const int*   col   = (const int*)d_in[9];
    const int*   mask1 = (const int*)d_in[10];
    const int*   mask2 = (const int*)d_in[11];

    int n = in_sizes[0] / HDIM;
    int e = in_sizes[7];

    float* out   = (float*)d_out;
    float* z_mp  = out;
    float* z_mp2 = out + (size_t)n * HDIM;
    float* x_rec = out + (size_t)2 * n * HDIM;

    int gGemm = (n + 127) / 128;
    int gEW   = (n * 16 + 255) / 256;
    int gSp   = (n + 15) / 16;
    int gE    = (e + 255) / 256;
    int gN    = (n + 255) / 256;

    static cudaStream_t s2 = nullptr;
    static cudaEvent_t evFork = nullptr, evCsr = nullptr, evSpmm = nullptr, evDone = nullptr;
    if (s2 == nullptr) {
        cudaStreamCreateWithFlags(&s2, cudaStreamNonBlocking);
        cudaEventCreateWithFlags(&evFork, cudaEventDisableTiming);
        cudaEventCreateWithFlags(&evCsr, cudaEventDisableTiming);
        cudaEventCreateWithFlags(&evSpmm, cudaEventDisableTiming);
        cudaEventCreateWithFlags(&evDone, cudaEventDisableTiming);
    }
    cudaStream_t s0 = 0;

    // ---- fork: CSR build on s2, pass-1 GEMM on main (independent) ----
    cudaEventRecord(evFork, s0);
    cudaStreamWaitEvent(s2, evFork, 0);

    csr_zero<<<gN, 256, 0, s2>>>(n);
    csr_hist<<<gE, 256, 0, s2>>>(row, e);
    csr_scan<<<1, 1024, 0, s2>>>(n);
    csr_scatter<<<gE, 256, 0, s2>>>(row, col, adj, mask1, mask2, e);
    cudaEventRecord(evCsr, s2);

    gemm_gcn_mma<<<gGemm, 128, 0, s0>>>(h, W, n);

    // ---- join: SpMM needs CSR + fts (also zeroes g_s[0..1]) ----
    cudaStreamWaitEvent(s0, evCsr, 0);
    spmm_dual_all<<<gSp, 256, 0, s0>>>(b, n);
    cudaEventRecord(evSpmm, s0);

    // ---- branch B on s2: sel=1 chain (z_mp2), independent of pass 3 ----
    cudaStreamWaitEvent(s2, evSpmm, 0);
    att_gemm_mma<<<dim3(gGemm, PNUM), 128, 0, s2>>>(1, a, fcw, fcb, n);
    combine_k<<<gEW, 256, 0, s2>>>(1, 0, a, att, z_mp2, n);
    cudaEventRecord(evDone, s2);

    // ---- main chain: sel=0 then pass 3 ----
    att_gemm_mma<<<dim3(gGemm, PNUM), 128, 0, s0>>>(0, a, fcw, fcb, n);
    combine_k<<<gEW, 256, 0, s0>>>(0, 1, a, att, z_mp, n);   // also writes g_z16

    gemm_gcn_mma_h<<<gGemm, 128, 0, s0>>>(W, n);
    spmm_mask_all<<<gSp, 256, 0, s0>>>(b, n);                // zeroes g_s[0]
    att_gemm_mma<<<dim3(gGemm, PNUM), 128, 0, s0>>>(0, a, fcw, fcb, n);
    combine_k<<<gEW, 256, 0, s0>>>(0, 0, a, att, x_rec, n);

    // ---- final join ----
    cudaStreamWaitEvent(s0, evDone, 0);
}